// round 6
// baseline (speedup 1.0000x reference)
#include <cuda_runtime.h>
#include <cuda_bf16.h>
#include <cstdint>

#define D_MODEL 2048
#define N_HEADS 16
#define D_FF    8192
#define BB      4
#define TT      1024
#define BT      (BB*TT)      // 4096 tokens
#define DH      128
#define BH      (BB*N_HEADS) // 64

// ---------------- scratch (device globals; no allocs allowed) ----------------
__device__ float g_q  [(long)BT*D_MODEL];   // [b,h,t,d]
__device__ float g_k  [(long)BT*D_MODEL];   // [b,h,t,d]
__device__ float g_vt [(long)BT*D_MODEL];   // [b,h,d,t]  (transposed V)
__device__ float g_sc [(long)BH*TT*TT];     // scores / probs (in-place)
__device__ float g_at [(long)BT*D_MODEL];   // attention output [b,t,h*d]
__device__ float g_x1 [(long)BT*D_MODEL];   // residual after O proj
__device__ float g_ff [(long)BT*D_FF];

// 2-term int8 quantized activations + per-row scale
__device__ __align__(16) int8_t g_p1d[(long)BT*D_MODEL];
__device__ __align__(16) int8_t g_p2d[(long)BT*D_MODEL];
__device__ float g_rsd[BT];
__device__ __align__(16) int8_t g_p1f[(long)BT*D_FF];
__device__ __align__(16) int8_t g_p2f[(long)BT*D_FF];
__device__ float g_rsf[BT];

// canonical int8 weights
#define NWD ((long)D_MODEL*D_MODEL)   // 4,194,304
#define NWF ((long)D_FF*D_MODEL)      // 16,777,216
__device__ __align__(16) int8_t g_w[(long)4*NWD + 2*NWF];
__device__ int g_cnt32;
__device__ int g_cntf;

// ---------------- dtype probe + weight normalization ----------------
__global__ void zero_counters() { g_cnt32 = 0; g_cntf = 0; }

__global__ void probe_dtype(const void* __restrict__ p, int nwords)
{
    int i = blockIdx.x * blockDim.x + threadIdx.x;
    if (i >= nwords) return;
    int v = ((const int*)p)[i];
    if (v < -127 || v > 127) atomicAdd(&g_cnt32, 1);
    float f = ((const float*)p)[i];
    bool okf = (f >= -127.0f) && (f <= 127.0f) && (f == rintf(f));
    if (!okf) atomicAdd(&g_cntf, 1);
}

__global__ void convert_w(const void* __restrict__ src, int8_t* __restrict__ dst, long n)
{
    long i = (long)blockIdx.x * blockDim.x + threadIdx.x;
    if (i >= n) return;
    int mode = (g_cnt32 == 0) ? 1 : ((g_cntf == 0) ? 2 : 0);  // 1=int32, 2=float32, 0=int8
    int8_t v;
    if (mode == 1)      v = (int8_t)((const int*)src)[i];
    else if (mode == 2) v = (int8_t)__float2int_rn(((const float*)src)[i]);
    else                v = ((const int8_t*)src)[i];
    dst[i] = v;
}

// ---------------- mma / ldmatrix / cp.async helpers ----------------
__device__ __forceinline__ void ldsm_x4(uint32_t& r0, uint32_t& r1, uint32_t& r2, uint32_t& r3, uint32_t a) {
    asm volatile("ldmatrix.sync.aligned.m8n8.x4.shared.b16 {%0,%1,%2,%3},[%4];"
                 : "=r"(r0), "=r"(r1), "=r"(r2), "=r"(r3) : "r"(a));
}
__device__ __forceinline__ void ldsm_x2(uint32_t& r0, uint32_t& r1, uint32_t a) {
    asm volatile("ldmatrix.sync.aligned.m8n8.x2.shared.b16 {%0,%1},[%2];"
                 : "=r"(r0), "=r"(r1) : "r"(a));
}
__device__ __forceinline__ void mma16816(float* c, uint32_t a0, uint32_t a1, uint32_t a2, uint32_t a3,
                                         uint32_t b0, uint32_t b1) {
    asm volatile("mma.sync.aligned.m16n8k16.row.col.f32.bf16.bf16.f32 "
                 "{%0,%1,%2,%3},{%4,%5,%6,%7},{%8,%9},{%0,%1,%2,%3};"
                 : "+f"(c[0]), "+f"(c[1]), "+f"(c[2]), "+f"(c[3])
                 : "r"(a0), "r"(a1), "r"(a2), "r"(a3), "r"(b0), "r"(b1));
}
__device__ __forceinline__ void imma16832(int* c, uint32_t a0, uint32_t a1, uint32_t a2, uint32_t a3,
                                          uint32_t b0, uint32_t b1) {
    asm volatile("mma.sync.aligned.m16n8k32.row.col.s32.s8.s8.s32 "
                 "{%0,%1,%2,%3},{%4,%5,%6,%7},{%8,%9},{%0,%1,%2,%3};"
                 : "+r"(c[0]), "+r"(c[1]), "+r"(c[2]), "+r"(c[3])
                 : "r"(a0), "r"(a1), "r"(a2), "r"(a3), "r"(b0), "r"(b1));
}
__device__ __forceinline__ void cp16(uint32_t dst, const void* src) {
    asm volatile("cp.async.cg.shared.global [%0], [%1], 16;"
                 :: "r"(dst), "l"(__cvta_generic_to_global(src)) : "memory");
}
__device__ __forceinline__ uint32_t smem_u32(const void* p) {
    uint32_t a;
    asm("{ .reg .u64 t; cvta.to.shared.u64 t, %1; cvt.u32.u64 %0, t; }" : "=r"(a) : "l"(p));
    return a;
}

// ============================================================================
// GEMM-I8 (int8 IMMA, 3-stage cp.async pipeline):
//   C = (A1 + A2/254) @ W^T  -> v = C * rs[row] * s[col]  (+bias) (+res)
// A1/A2: [M][K] int8 row-major; W: [N][K] int8 row-major.
// CTA tile 128x128, K-block 128 int8. 8 warps (2M x 4N), warp tile 64x32.
// Smem per stage: A1 16K + A2 16K + B 16K (128B rows, chunk-XOR swizzle).
// LAYOUT: 0 = out[r*ldc+c], 1 = q/k head layout, 2 = transposed-V layout
// ============================================================================
#define IST 49152                     // bytes per stage
#define SI_A1(s) ((s)*IST)
#define SI_A2(s) ((s)*IST + 16384)
#define SI_B(s)  ((s)*IST + 32768)
#define SMEM_I   (3*IST)              // 147456 bytes

template<int LAYOUT, bool HAS_BIAS, bool HAS_RES>
__global__ void __launch_bounds__(256) gemm_i8(
    const int8_t* __restrict__ A1, const int8_t* __restrict__ A2,
    const float* __restrict__ rs, int K, const int8_t* __restrict__ W,
    const float* __restrict__ s, const float* __restrict__ bias,
    const float* __restrict__ res, float* __restrict__ out, int ldc)
{
    extern __shared__ char smem[];
    const uint32_t sb = smem_u32(smem);
    const int tid = threadIdx.x, lane = tid & 31, w = tid >> 5;
    const int wm = w & 1, wn = w >> 1;           // warp grid 2(M) x 4(N)
    const int m0 = blockIdx.y * 128, n0 = blockIdx.x * 128;
    const int KB = K >> 7;                        // 128 int8 per block

    const int8_t* A1g = A1 + (long)m0 * K;
    const int8_t* A2g = A2 + (long)m0 * K;
    const int8_t* Bg  = W  + (long)n0 * K;

    const int lr = tid >> 3, lj = tid & 7;       // 32 rows x 8 chunks per pass

    auto load_stage = [&](int st, int kb) {
        const int8_t* a1 = A1g + kb * 128;
        const int8_t* a2 = A2g + kb * 128;
        const int8_t* b  = Bg  + kb * 128;
        #pragma unroll
        for (int i = 0; i < 4; i++) {
            int r = lr + i * 32;
            uint32_t dsw = r * 128 + ((lj ^ (r & 7)) * 16);
            cp16(sb + SI_A1(st) + dsw, a1 + (long)r * K + lj * 16);
        }
        #pragma unroll
        for (int i = 0; i < 4; i++) {
            int r = lr + i * 32;
            uint32_t dsw = r * 128 + ((lj ^ (r & 7)) * 16);
            cp16(sb + SI_A2(st) + dsw, a2 + (long)r * K + lj * 16);
        }
        #pragma unroll
        for (int i = 0; i < 4; i++) {
            int r = lr + i * 32;
            uint32_t dsw = r * 128 + ((lj ^ (r & 7)) * 16);
            cp16(sb + SI_B(st) + dsw, b + (long)r * K + lj * 16);
        }
        asm volatile("cp.async.commit_group;" ::: "memory");
    };

    int acc1[4][4][4], acc2[4][4][4];
    #pragma unroll
    for (int i = 0; i < 4; i++)
        #pragma unroll
        for (int j = 0; j < 4; j++)
            #pragma unroll
            for (int e = 0; e < 4; e++) { acc1[i][j][e] = 0; acc2[i][j][e] = 0; }

    load_stage(0, 0);
    load_stage(1, 1);

    for (int kb = 0; kb < KB; kb++) {
        const int st = kb % 3;
        asm volatile("cp.async.wait_group 1;" ::: "memory");
        __syncthreads();
        if (kb + 2 < KB) load_stage((kb + 2) % 3, kb + 2);

        const uint32_t a1B = sb + SI_A1(st), a2B = sb + SI_A2(st), bB = sb + SI_B(st);
        // rows hold 64 elem16 (=128 int8); k32 step = 16 elem16 -> 4 steps
        #pragma unroll
        for (int ks = 0; ks < 4; ks++) {
            const int kk0 = ks * 16;
            uint32_t af[4][4], bf[4][2];
            #pragma unroll
            for (int j = 0; j < 4; j++) {
                int rb = wn * 32 + j * 8 + (lane & 7);
                int kk = kk0 + ((lane >> 3) & 1) * 8;
                uint32_t bd = bB + rb * 128 + (((kk >> 3) ^ (rb & 7)) * 16);
                ldsm_x2(bf[j][0], bf[j][1], bd);
            }
            #pragma unroll
            for (int i = 0; i < 4; i++) {
                int ra = wm * 64 + i * 16 + (lane & 15);
                int kk = kk0 + (lane >> 4) * 8;
                uint32_t ad = a1B + ra * 128 + (((kk >> 3) ^ (ra & 7)) * 16);
                ldsm_x4(af[i][0], af[i][1], af[i][2], af[i][3], ad);
            }
            #pragma unroll
            for (int i = 0; i < 4; i++)
                #pragma unroll
                for (int j = 0; j < 4; j++)
                    imma16832(acc1[i][j], af[i][0], af[i][1], af[i][2], af[i][3], bf[j][0], bf[j][1]);
            #pragma unroll
            for (int i = 0; i < 4; i++) {
                int ra = wm * 64 + i * 16 + (lane & 15);
                int kk = kk0 + (lane >> 4) * 8;
                uint32_t ad = a2B + ra * 128 + (((kk >> 3) ^ (ra & 7)) * 16);
                ldsm_x4(af[i][0], af[i][1], af[i][2], af[i][3], ad);
            }
            #pragma unroll
            for (int i = 0; i < 4; i++)
                #pragma unroll
                for (int j = 0; j < 4; j++)
                    imma16832(acc2[i][j], af[i][0], af[i][1], af[i][2], af[i][3], bf[j][0], bf[j][1]);
        }
    }

    // --- epilogue: v = (acc1 + acc2/254) * rs[r] * s[c] (+bias) (+res) ---
    const int gr = lane >> 2, gc = (lane & 3) * 2;
    #pragma unroll
    for (int i = 0; i < 4; i++) {
        #pragma unroll
        for (int j = 0; j < 4; j++) {
            int rbase = m0 + wm * 64 + i * 16 + gr;
            int cbase = n0 + wn * 32 + j * 8 + gc;
            #pragma unroll
            for (int e = 0; e < 4; e++) {
                int r = rbase + (e >> 1) * 8;
                int c = cbase + (e & 1);
                float v = ((float)acc1[i][j][e] + (float)acc2[i][j][e] * (1.0f / 254.0f)) * rs[r] * s[c];
                if (HAS_BIAS) v += bias[c];
                if (HAS_RES)  v += res[(long)r * D_MODEL + c];
                long idx;
                if (LAYOUT == 0) {
                    idx = (long)r * ldc + c;
                } else {
                    int b = r >> 10, t = r & 1023, h = c >> 7, d = c & 127;
                    if (LAYOUT == 1) idx = (long)(b * N_HEADS + h) * (TT * DH) + (long)t * DH + d;
                    else             idx = (long)(b * N_HEADS + h) * (TT * DH) + (long)d * TT + t;
                }
                out[idx] = v;
            }
        }
    }
}

// ============================================================================
// GEMM-P: C[M,N] = A_f32[M,K] @ B_f32[N,K]^T   (both split, triple-K)
// EPI: 0 = scores (x 1/sqrt(128)),  1 = P@V (scatter to [b,t,h*128+d])
// ============================================================================
template<int EPI>
__global__ void __launch_bounds__(256) gemm_p(
    const float* __restrict__ Ab, const float* __restrict__ Bb,
    float* __restrict__ outb, int K, int lda, int ldb, long sAz, long sBz)
{
    constexpr int ST = 56;
    __shared__ __align__(16) __nv_bfloat16 sA[128 * ST];
    __shared__ __align__(16) __nv_bfloat16 sB[128 * ST];

    const int z = blockIdx.z;
    const float* A = Ab + (long)z * sAz;
    const float* B = Bb + (long)z * sBz;

    const int tid = threadIdx.x, lane = tid & 31, w = tid >> 5;
    const int wm = w & 1, wn = w >> 1;
    const int m0 = blockIdx.y * 128, n0 = blockIdx.x * 128;
    const int tg = lane >> 2, tk = (lane & 3) * 2;

    float acc[4][4][4];
    #pragma unroll
    for (int i = 0; i < 4; i++)
        #pragma unroll
        for (int j = 0; j < 4; j++)
            #pragma unroll
            for (int e = 0; e < 4; e++) acc[i][j][e] = 0.f;

    const int la_k = tid & 15, la_r = tid >> 4;

    for (int kb = 0; kb < K; kb += 16) {
        #pragma unroll
        for (int it = 0; it < 8; it++) {
            int r = la_r + it * 16;
            float va = A[(long)(m0 + r) * lda + kb + la_k];
            __nv_bfloat16 hi = __float2bfloat16(va);
            __nv_bfloat16 lo = __float2bfloat16(va - __bfloat162float(hi));
            sA[r * ST + 3 * la_k]     = hi;
            sA[r * ST + 3 * la_k + 1] = lo;
            sA[r * ST + 3 * la_k + 2] = hi;
            float vb = B[(long)(n0 + r) * ldb + kb + la_k];
            hi = __float2bfloat16(vb);
            lo = __float2bfloat16(vb - __bfloat162float(hi));
            sB[r * ST + 3 * la_k]     = hi;
            sB[r * ST + 3 * la_k + 1] = hi;
            sB[r * ST + 3 * la_k + 2] = lo;
        }
        __syncthreads();
        #pragma unroll
        for (int ks = 0; ks < 3; ks++) {
            const int kk0 = ks * 16;
            uint32_t af[4][4], bf[4][2];
            #pragma unroll
            for (int i = 0; i < 4; i++) {
                int ra = wm * 64 + i * 16 + tg;
                af[i][0] = *(const uint32_t*)&sA[(ra    ) * ST + kk0 + tk    ];
                af[i][1] = *(const uint32_t*)&sA[(ra + 8) * ST + kk0 + tk    ];
                af[i][2] = *(const uint32_t*)&sA[(ra    ) * ST + kk0 + tk + 8];
                af[i][3] = *(const uint32_t*)&sA[(ra + 8) * ST + kk0 + tk + 8];
            }
            #pragma unroll
            for (int j = 0; j < 4; j++) {
                int rb = wn * 32 + j * 8 + tg;
                bf[j][0] = *(const uint32_t*)&sB[rb * ST + kk0 + tk    ];
                bf[j][1] = *(const uint32_t*)&sB[rb * ST + kk0 + tk + 8];
            }
            #pragma unroll
            for (int i = 0; i < 4; i++)
                #pragma unroll
                for (int j = 0; j < 4; j++)
                    mma16816(acc[i][j], af[i][0], af[i][1], af[i][2], af[i][3], bf[j][0], bf[j][1]);
        }
        __syncthreads();
    }

    const int gr = tg, gc = tk;
    #pragma unroll
    for (int i = 0; i < 4; i++) {
        #pragma unroll
        for (int j = 0; j < 4; j++) {
            int rbase = m0 + wm * 64 + i * 16 + gr;
            int cbase = n0 + wn * 32 + j * 8 + gc;
            #pragma unroll
            for (int e = 0; e < 4; e++) {
                int r = rbase + (e >> 1) * 8;
                int c = cbase + (e & 1);
                float v = acc[i][j][e];
                if (EPI == 0) {
                    outb[(long)z * TT * TT + (long)r * TT + c] = v * 0.08838834764831845f;
                } else {
                    int b = z >> 4, h = z & 15;
                    outb[((long)(b * TT + r)) * D_MODEL + h * DH + c] = v;
                }
            }
        }
    }
}

// ---------------- reductions ----------------
__device__ __forceinline__ float warp_sum(float v) {
    #pragma unroll
    for (int o = 16; o; o >>= 1) v += __shfl_xor_sync(0xffffffffu, v, o);
    return v;
}
__device__ __forceinline__ float warp_max(float v) {
    #pragma unroll
    for (int o = 16; o; o >>= 1) v = fmaxf(v, __shfl_xor_sync(0xffffffffu, v, o));
    return v;
}
template<int NW>
__device__ __forceinline__ float block_sum(float v, float* buf) {
    int tid = threadIdx.x;
    v = warp_sum(v);
    __syncthreads();
    if ((tid & 31) == 0) buf[tid >> 5] = v;
    __syncthreads();
    if (tid == 0) { float t = 0; for (int i = 0; i < NW; i++) t += buf[i]; buf[0] = t; }
    __syncthreads();
    return buf[0];
}
template<int NW>
__device__ __forceinline__ float block_max(float v, float* buf) {
    int tid = threadIdx.x;
    v = warp_max(v);
    __syncthreads();
    if ((tid & 31) == 0) buf[tid >> 5] = v;
    __syncthreads();
    if (tid == 0) { float t = buf[0]; for (int i = 1; i < NW; i++) t = fmaxf(t, buf[i]); buf[0] = t; }
    __syncthreads();
    return buf[0];
}

// quantize v (given row scale s, inv=1/s) into 2 int8 terms
__device__ __forceinline__ void quant2(float v, float sc, float inv, int8_t& o1, int8_t& o2) {
    int i1 = __float2int_rn(v * inv);
    i1 = max(-127, min(127, i1));
    float r1 = v - sc * (float)i1;
    int i2 = __float2int_rn(r1 * (254.0f * inv));
    i2 = max(-127, min(127, i2));
    o1 = (int8_t)i1; o2 = (int8_t)i2;
}

// ------- LN (optional) + Hadamard-2048 -> 2-term int8 planes + row scale -------
template<bool DO_LN>
__global__ void __launch_bounds__(256) ln_had2048(
    const float* __restrict__ in, const float* __restrict__ g,
    const float* __restrict__ bta, int8_t* __restrict__ p1,
    int8_t* __restrict__ p2, float* __restrict__ rsv)
{
    __shared__ float s[2048];
    __shared__ float red[8];
    const int tid = threadIdx.x;
    const float* x = in + (long)blockIdx.x * 2048;
    float loc[8];
    #pragma unroll
    for (int j = 0; j < 8; j++) loc[j] = x[tid + 256 * j];

    if (DO_LN) {
        float sm = 0.f, sq = 0.f;
        #pragma unroll
        for (int j = 0; j < 8; j++) { sm += loc[j]; sq += loc[j] * loc[j]; }
        float S  = block_sum<8>(sm, red);
        float SQ = block_sum<8>(sq, red);
        float mu = S * (1.0f / 2048.0f);
        float var = SQ * (1.0f / 2048.0f) - mu * mu;
        float inv = rsqrtf(var + 1e-5f);
        #pragma unroll
        for (int j = 0; j < 8; j++) {
            int c = tid + 256 * j;
            loc[j] = (loc[j] - mu) * inv * g[c] + bta[c];
        }
    }
    #pragma unroll
    for (int j = 0; j < 8; j++) s[tid + 256 * j] = loc[j];

    int sh = 0;
    for (int h = 1; h < 2048; h <<= 1, sh++) {
        __syncthreads();
        #pragma unroll
        for (int j = 0; j < 4; j++) {
            int pi = tid + 256 * j;
            int idx = ((pi >> sh) << (sh + 1)) + (pi & (h - 1));
            float a = s[idx], c = s[idx + h];
            s[idx] = a + c;
            s[idx + h] = a - c;
        }
    }
    __syncthreads();
    float mx = 0.f;
    float vv[8];
    #pragma unroll
    for (int j = 0; j < 8; j++) {
        vv[j] = s[tid + 256 * j] * 0.022097086912079608f;
        mx = fmaxf(mx, fabsf(vv[j]));
    }
    float rmax = block_max<8>(mx, red);
    float sc = rmax * (1.0f / 127.0f) + 1e-30f;
    float inv = 1.0f / sc;
    if (tid == 0) rsv[blockIdx.x] = sc;
    int8_t* o1 = p1 + (long)blockIdx.x * 2048;
    int8_t* o2 = p2 + (long)blockIdx.x * 2048;
    #pragma unroll
    for (int j = 0; j < 8; j++) {
        int c = tid + 256 * j;
        quant2(vv[j], sc, inv, o1[c], o2[c]);
    }
}

// ------- GELU(exact) + Hadamard-8192 -> 2-term int8 planes + row scale -------
__global__ void __launch_bounds__(512) gelu_had8192(
    const float* __restrict__ in, int8_t* __restrict__ p1,
    int8_t* __restrict__ p2, float* __restrict__ rsv)
{
    __shared__ float s[8192];
    __shared__ float red[16];
    const int tid = threadIdx.x;
    const float* x = in + (long)blockIdx.x * 8192;
    #pragma unroll
    for (int j = 0; j < 16; j++) {
        float v = x[tid + 512 * j];
        v = 0.5f * v * (1.0f + erff(v * 0.7071067811865476f));
        s[tid + 512 * j] = v;
    }
    int sh = 0;
    for (int h = 1; h < 8192; h <<= 1, sh++) {
        __syncthreads();
        #pragma unroll
        for (int j = 0; j < 8; j++) {
            int pi = tid + 512 * j;
            int idx = ((pi >> sh) << (sh + 1)) + (pi & (h - 1));
            float a = s[idx], c = s[idx + h];
            s[idx] = a + c;
            s[idx + h] = a - c;
        }
    }
    __syncthreads();
    float mx = 0.f;
    float vv[16];
    #pragma unroll
    for (int j = 0; j < 16; j++) {
        vv[j] = s[tid + 512 * j] * 0.011048543456039806f;
        mx = fmaxf(mx, fabsf(vv[j]));
    }
    float rmax = block_max<16>(mx, red);
    float sc = rmax * (1.0f / 127.0f) + 1e-30f;
    float inv = 1.0f / sc;
    if (tid == 0) rsv[blockIdx.x] = sc;
    int8_t* o1 = p1 + (long)blockIdx.x * 8192;
    int8_t* o2 = p2 + (long)blockIdx.x * 8192;
    #pragma unroll
    for (int j = 0; j < 16; j++) {
        int c = tid + 512 * j;
        quant2(vv[j], sc, inv, o1[c], o2[c]);
    }
}

// ---------------- softmax over rows of 1024 (in-place) ----------------
__global__ void __launch_bounds__(256) softmax1024(float* __restrict__ sc)
{
    __shared__ float red[8];
    const int tid = threadIdx.x;
    float* row = sc + (long)blockIdx.x * 1024;
    float v[4];
    float mx = -3.4e38f;
    #pragma unroll
    for (int j = 0; j < 4; j++) { v[j] = row[tid + 256 * j]; mx = fmaxf(mx, v[j]); }
    float m = block_max<8>(mx, red);
    float sm = 0.f;
    #pragma unroll
    for (int j = 0; j < 4; j++) { v[j] = __expf(v[j] - m); sm += v[j]; }
    float S = block_sum<8>(sm, red);
    float inv = 1.0f / S;
    #pragma unroll
    for (int j = 0; j < 4; j++) row[tid + 256 * j] = v[j] * inv;
}

// ============================================================================
extern "C" void kernel_launch(void* const* d_in, const int* in_sizes, int n_in,
                              void* d_out, int out_size)
{
    const float*  x    = (const float*) d_in[0];
    const float*  ln1g = (const float*) d_in[1];
    const float*  ln1b = (const float*) d_in[2];
    const float*  ln2g = (const float*) d_in[3];
    const float*  ln2b = (const float*) d_in[4];
    const void*   Qq   = d_in[5];
    const float*  sq   = (const float*) d_in[6];
    const void*   Qk   = d_in[7];
    const float*  sk   = (const float*) d_in[8];
    const void*   Qv   = d_in[9];
    const float*  sv   = (const float*) d_in[10];
    const void*   Qo   = d_in[11];
    const float*  so   = (const float*) d_in[12];
    const void*   Qf1  = d_in[13];
    const float*  sf1  = (const float*) d_in[14];
    const float*  bf1  = (const float*) d_in[15];
    const void*   Qf2  = d_in[16];
    const float*  sf2  = (const float*) d_in[17];
    const float*  bf2  = (const float*) d_in[18];
    float* out = (float*)d_out;

    float *q, *k, *vt, *sc, *at, *x1, *ff, *rsd, *rsf;
    int8_t *p1d, *p2d, *p1f, *p2f, *wbase;
    cudaGetSymbolAddress((void**)&q,    g_q);
    cudaGetSymbolAddress((void**)&k,    g_k);
    cudaGetSymbolAddress((void**)&vt,   g_vt);
    cudaGetSymbolAddress((void**)&sc,   g_sc);
    cudaGetSymbolAddress((void**)&at,   g_at);
    cudaGetSymbolAddress((void**)&x1,   g_x1);
    cudaGetSymbolAddress((void**)&ff,   g_ff);
    cudaGetSymbolAddress((void**)&p1d,  g_p1d);
    cudaGetSymbolAddress((void**)&p2d,  g_p2d);
    cudaGetSymbolAddress((void**)&rsd,  g_rsd);
    cudaGetSymbolAddress((void**)&p1f,  g_p1f);
    cudaGetSymbolAddress((void**)&p2f,  g_p2f);
    cudaGetSymbolAddress((void**)&rsf,  g_rsf);
    cudaGetSymbolAddress((void**)&wbase, g_w);

    int8_t* wq  = wbase;
    int8_t* wk  = wbase + NWD;
    int8_t* wv  = wbase + 2 * NWD;
    int8_t* wo  = wbase + 3 * NWD;
    int8_t* wf1 = wbase + 4 * NWD;
    int8_t* wf2 = wbase + 4 * NWD + NWF;

    cudaFuncSetAttribute((const void*)gemm_i8<1, false, false>, cudaFuncAttributeMaxDynamicSharedMemorySize, SMEM_I);
    cudaFuncSetAttribute((const void*)gemm_i8<2, false, false>, cudaFuncAttributeMaxDynamicSharedMemorySize, SMEM_I);
    cudaFuncSetAttribute((const void*)gemm_i8<0, false, true>,  cudaFuncAttributeMaxDynamicSharedMemorySize, SMEM_I);
    cudaFuncSetAttribute((const void*)gemm_i8<0, true, false>,  cudaFuncAttributeMaxDynamicSharedMemorySize, SMEM_I);
    cudaFuncSetAttribute((const void*)gemm_i8<0, true, true>,   cudaFuncAttributeMaxDynamicSharedMemorySize, SMEM_I);

    // 0. dtype probe + normalize weights to int8
    zero_counters<<<1, 1>>>();
    probe_dtype<<<4096, 256>>>(Qq, 1 << 20);
    convert_w<<<(int)((NWD + 255) / 256), 256>>>(Qq,  wq,  NWD);
    convert_w<<<(int)((NWD + 255) / 256), 256>>>(Qk,  wk,  NWD);
    convert_w<<<(int)((NWD + 255) / 256), 256>>>(Qv,  wv,  NWD);
    convert_w<<<(int)((NWD + 255) / 256), 256>>>(Qo,  wo,  NWD);
    convert_w<<<(int)((NWF + 255) / 256), 256>>>(Qf1, wf1, NWF);
    convert_w<<<(int)((NWF + 255) / 256), 256>>>(Qf2, wf2, NWF);

    // 1. LN1 + Hadamard -> int8 2-term
    ln_had2048<true><<<BT, 256>>>(x, ln1g, ln1b, p1d, p2d, rsd);
    // 2-4. Q/K/V projections (int8 IMMA)
    gemm_i8<1, false, false><<<dim3(16, 32), 256, SMEM_I>>>(p1d, p2d, rsd, D_MODEL, wq, sq, nullptr, nullptr, q,  0);
    gemm_i8<1, false, false><<<dim3(16, 32), 256, SMEM_I>>>(p1d, p2d, rsd, D_MODEL, wk, sk, nullptr, nullptr, k,  0);
    gemm_i8<2, false, false><<<dim3(16, 32), 256, SMEM_I>>>(p1d, p2d, rsd, D_MODEL, wv, sv, nullptr, nullptr, vt, 0);
    // 5. scores = q @ k^T / sqrt(128)
    gemm_p<0><<<dim3(8, 8, BH), 256>>>(q, k, sc, DH, DH, DH, (long)TT * DH, (long)TT * DH);
    // 6. softmax
    softmax1024<<<BH * TT, 256>>>(sc);
    // 7. attn = P @ V
    gemm_p<1><<<dim3(1, 8, BH), 256>>>(sc, vt, at, TT, TT, TT, (long)TT * TT, (long)DH * TT);
    // 8. Hadamard(attn) -> int8 2-term
    ln_had2048<false><<<BT, 256>>>(at, nullptr, nullptr, p1d, p2d, rsd);
    // 9. x1 = x + O-proj
    gemm_i8<0, false, true><<<dim3(16, 32), 256, SMEM_I>>>(p1d, p2d, rsd, D_MODEL, wo, so, nullptr, x, x1, D_MODEL);
    // 10. LN2 + Hadamard -> int8 2-term
    ln_had2048<true><<<BT, 256>>>(x1, ln2g, ln2b, p1d, p2d, rsd);
    // 11. FF1 (+bias)
    gemm_i8<0, true, false><<<dim3(64, 32), 256, SMEM_I>>>(p1d, p2d, rsd, D_MODEL, wf1, sf1, bf1, nullptr, ff, D_FF);
    // 12. GELU + Hadamard-8192 -> int8 2-term
    gelu_had8192<<<BT, 512>>>(ff, p1f, p2f, rsf);
    // 13. out = x1 + FF2 (+bias)
    gemm_i8<0, true, true><<<dim3(16, 32), 256, SMEM_I>>>(p1f, p2f, rsf, D_FF, wf2, sf2, bf2, x1, out, D_MODEL);
}

// round 7
// speedup vs baseline: 3.3078x; 3.3078x over previous
#include <cuda_runtime.h>
#include <cuda_bf16.h>
#include <cuda_fp16.h>
#include <cstdint>

#define D_MODEL 2048
#define N_HEADS 16
#define D_FF    8192
#define BB      4
#define TT      1024
#define BT      (BB*TT)      // 4096 tokens
#define DH      128
#define BH      (BB*N_HEADS) // 64

// ---------------- scratch (device globals; no allocs allowed) ----------------
__device__ float g_q  [(long)BT*D_MODEL];   // [b,h,t,d]
__device__ float g_k  [(long)BT*D_MODEL];   // [b,h,t,d]
__device__ float g_vt [(long)BT*D_MODEL];   // [b,h,d,t]  (transposed V)
__device__ float g_sc [(long)BH*TT*TT];     // scores / probs (in-place)
__device__ float g_at [(long)BT*D_MODEL];   // attention output [b,t,h*d]
__device__ float g_x1 [(long)BT*D_MODEL];   // residual after O proj
__device__ float g_ff [(long)BT*D_FF];

// fp16 activations (single term; reused across stages)
__device__ __align__(16) __half g_hd[(long)BT*D_MODEL];
__device__ __align__(16) __half g_hf[(long)BT*D_FF];

// fp16 weights (int8 values are exact in fp16)
#define NWD ((long)D_MODEL*D_MODEL)   // 4,194,304
#define NWF ((long)D_FF*D_MODEL)      // 16,777,216
__device__ __align__(16) __half g_w[(long)4*NWD + 2*NWF];
__device__ int g_cnt32;
__device__ int g_cntf;

// ---------------- dtype probe + weight normalization ----------------
__global__ void zero_counters() { g_cnt32 = 0; g_cntf = 0; }

__global__ void probe_dtype(const void* __restrict__ p, int nwords)
{
    int i = blockIdx.x * blockDim.x + threadIdx.x;
    if (i >= nwords) return;
    int v = ((const int*)p)[i];
    if (v < -127 || v > 127) atomicAdd(&g_cnt32, 1);
    float f = ((const float*)p)[i];
    bool okf = (f >= -127.0f) && (f <= 127.0f) && (f == rintf(f));
    if (!okf) atomicAdd(&g_cntf, 1);
}

__global__ void convert_w(const void* __restrict__ src, __half* __restrict__ dst, long n)
{
    long i = (long)blockIdx.x * blockDim.x + threadIdx.x;
    if (i >= n) return;
    int mode = (g_cnt32 == 0) ? 1 : ((g_cntf == 0) ? 2 : 0);  // 1=int32, 2=float32, 0=int8
    signed char v;
    if (mode == 1)      v = (signed char)((const int*)src)[i];
    else if (mode == 2) v = (signed char)__float2int_rn(((const float*)src)[i]);
    else                v = ((const signed char*)src)[i];
    dst[i] = __float2half_rn((float)v);
}

// ---------------- mma / ldmatrix / cp.async helpers ----------------
__device__ __forceinline__ void ldsm_x4(uint32_t& r0, uint32_t& r1, uint32_t& r2, uint32_t& r3, uint32_t a) {
    asm volatile("ldmatrix.sync.aligned.m8n8.x4.shared.b16 {%0,%1,%2,%3},[%4];"
                 : "=r"(r0), "=r"(r1), "=r"(r2), "=r"(r3) : "r"(a));
}
__device__ __forceinline__ void ldsm_x2(uint32_t& r0, uint32_t& r1, uint32_t a) {
    asm volatile("ldmatrix.sync.aligned.m8n8.x2.shared.b16 {%0,%1},[%2];"
                 : "=r"(r0), "=r"(r1) : "r"(a));
}
__device__ __forceinline__ void mma16816(float* c, uint32_t a0, uint32_t a1, uint32_t a2, uint32_t a3,
                                         uint32_t b0, uint32_t b1) {
    asm volatile("mma.sync.aligned.m16n8k16.row.col.f32.bf16.bf16.f32 "
                 "{%0,%1,%2,%3},{%4,%5,%6,%7},{%8,%9},{%0,%1,%2,%3};"
                 : "+f"(c[0]), "+f"(c[1]), "+f"(c[2]), "+f"(c[3])
                 : "r"(a0), "r"(a1), "r"(a2), "r"(a3), "r"(b0), "r"(b1));
}
__device__ __forceinline__ void mma16816h(float* c, uint32_t a0, uint32_t a1, uint32_t a2, uint32_t a3,
                                          uint32_t b0, uint32_t b1) {
    asm volatile("mma.sync.aligned.m16n8k16.row.col.f32.f16.f16.f32 "
                 "{%0,%1,%2,%3},{%4,%5,%6,%7},{%8,%9},{%0,%1,%2,%3};"
                 : "+f"(c[0]), "+f"(c[1]), "+f"(c[2]), "+f"(c[3])
                 : "r"(a0), "r"(a1), "r"(a2), "r"(a3), "r"(b0), "r"(b1));
}
__device__ __forceinline__ void cp16(uint32_t dst, const void* src) {
    asm volatile("cp.async.cg.shared.global [%0], [%1], 16;"
                 :: "r"(dst), "l"(__cvta_generic_to_global(src)) : "memory");
}
__device__ __forceinline__ uint32_t smem_u32(const void* p) {
    uint32_t a;
    asm("{ .reg .u64 t; cvta.to.shared.u64 t, %1; cvt.u32.u64 %0, t; }" : "=r"(a) : "l"(p));
    return a;
}

// ============================================================================
// GEMM-H (fp16 single-term, cp.async 3-stage pipeline):
//   C[M=4096, N] = A[M, K] @ W[N, K]^T  then *s[col] (+bias) (+res)
// A fp16 activations, W fp16 weights (exact int8). CTA tile 128x128,
// K-block 64 fp16 (128B rows, chunk-XOR swizzle). 8 warps (2M x 4N).
// LAYOUT: 0 = out[r*ldc+c], 1 = q/k head layout, 2 = transposed-V layout
// ============================================================================
#define HST 32768                     // bytes per stage (A 16K + B 16K)
#define SH_A(s) ((s)*HST)
#define SH_B(s) ((s)*HST + 16384)
#define SMEM_H  (3*HST)               // 98304 bytes

template<int LAYOUT, bool HAS_BIAS, bool HAS_RES>
__global__ void __launch_bounds__(256) gemm_h(
    const __half* __restrict__ A, const __half* __restrict__ W, int K,
    const float* __restrict__ s, const float* __restrict__ bias,
    const float* __restrict__ res, float* __restrict__ out, int ldc)
{
    extern __shared__ char smem[];
    const uint32_t sb = smem_u32(smem);
    const int tid = threadIdx.x, lane = tid & 31, w = tid >> 5;
    const int wm = w & 1, wn = w >> 1;           // warp grid 2(M) x 4(N)
    const int m0 = blockIdx.y * 128, n0 = blockIdx.x * 128;
    const int KB = K >> 6;

    const __half* Ag = A + (long)m0 * K;
    const __half* Bg = W + (long)n0 * K;

    const int lr = tid >> 3, lj = tid & 7;

    auto load_stage = [&](int st, int kb) {
        const __half* a = Ag + kb * 64;
        const __half* b = Bg + kb * 64;
        #pragma unroll
        for (int i = 0; i < 4; i++) {
            int r = lr + i * 32;
            uint32_t dsw = r * 128 + ((lj ^ (r & 7)) * 16);
            cp16(sb + SH_A(st) + dsw, a + (long)r * K + lj * 8);
        }
        #pragma unroll
        for (int i = 0; i < 4; i++) {
            int r = lr + i * 32;
            uint32_t dsw = r * 128 + ((lj ^ (r & 7)) * 16);
            cp16(sb + SH_B(st) + dsw, b + (long)r * K + lj * 8);
        }
        asm volatile("cp.async.commit_group;" ::: "memory");
    };

    float acc[4][4][4];
    #pragma unroll
    for (int i = 0; i < 4; i++)
        #pragma unroll
        for (int j = 0; j < 4; j++)
            #pragma unroll
            for (int e = 0; e < 4; e++) acc[i][j][e] = 0.f;

    load_stage(0, 0);
    load_stage(1, 1);

    for (int kb = 0; kb < KB; kb++) {
        const int st = kb % 3;
        asm volatile("cp.async.wait_group 1;" ::: "memory");
        __syncthreads();
        if (kb + 2 < KB) load_stage((kb + 2) % 3, kb + 2);

        const uint32_t aB = sb + SH_A(st), bB = sb + SH_B(st);
        #pragma unroll
        for (int ks = 0; ks < 4; ks++) {
            const int kk0 = ks * 16;
            uint32_t af[4][4], bf[4][2];
            #pragma unroll
            for (int i = 0; i < 4; i++) {
                int ra = wm * 64 + i * 16 + (lane & 15);
                int kk = kk0 + (lane >> 4) * 8;
                uint32_t ad = aB + ra * 128 + (((kk >> 3) ^ (ra & 7)) * 16);
                ldsm_x4(af[i][0], af[i][1], af[i][2], af[i][3], ad);
            }
            #pragma unroll
            for (int j = 0; j < 4; j++) {
                int rb = wn * 32 + j * 8 + (lane & 7);
                int kk = kk0 + ((lane >> 3) & 1) * 8;
                uint32_t bd = bB + rb * 128 + (((kk >> 3) ^ (rb & 7)) * 16);
                ldsm_x2(bf[j][0], bf[j][1], bd);
            }
            #pragma unroll
            for (int i = 0; i < 4; i++)
                #pragma unroll
                for (int j = 0; j < 4; j++)
                    mma16816h(acc[i][j], af[i][0], af[i][1], af[i][2], af[i][3], bf[j][0], bf[j][1]);
        }
    }

    // --- epilogue ---
    const int gr = lane >> 2, gc = (lane & 3) * 2;
    #pragma unroll
    for (int i = 0; i < 4; i++) {
        #pragma unroll
        for (int j = 0; j < 4; j++) {
            int rbase = m0 + wm * 64 + i * 16 + gr;
            int cbase = n0 + wn * 32 + j * 8 + gc;
            #pragma unroll
            for (int e = 0; e < 4; e++) {
                int r = rbase + (e >> 1) * 8;
                int c = cbase + (e & 1);
                float v = acc[i][j][e] * s[c];
                if (HAS_BIAS) v += bias[c];
                if (HAS_RES)  v += res[(long)r * D_MODEL + c];
                long idx;
                if (LAYOUT == 0) {
                    idx = (long)r * ldc + c;
                } else {
                    int b = r >> 10, t = r & 1023, h = c >> 7, d = c & 127;
                    if (LAYOUT == 1) idx = (long)(b * N_HEADS + h) * (TT * DH) + (long)t * DH + d;
                    else             idx = (long)(b * N_HEADS + h) * (TT * DH) + (long)d * TT + t;
                }
                out[idx] = v;
            }
        }
    }
}

// ============================================================================
// GEMM-P: C[M,N] = A_f32[M,K] @ B_f32[N,K]^T   (both split, triple-K bf16)
// EPI: 0 = scores (x 1/sqrt(128)),  1 = P@V (scatter to [b,t,h*128+d])
// ============================================================================
template<int EPI>
__global__ void __launch_bounds__(256) gemm_p(
    const float* __restrict__ Ab, const float* __restrict__ Bb,
    float* __restrict__ outb, int K, int lda, int ldb, long sAz, long sBz)
{
    constexpr int ST = 56;
    __shared__ __align__(16) __nv_bfloat16 sA[128 * ST];
    __shared__ __align__(16) __nv_bfloat16 sB[128 * ST];

    const int z = blockIdx.z;
    const float* A = Ab + (long)z * sAz;
    const float* B = Bb + (long)z * sBz;

    const int tid = threadIdx.x, lane = tid & 31, w = tid >> 5;
    const int wm = w & 1, wn = w >> 1;
    const int m0 = blockIdx.y * 128, n0 = blockIdx.x * 128;
    const int tg = lane >> 2, tk = (lane & 3) * 2;

    float acc[4][4][4];
    #pragma unroll
    for (int i = 0; i < 4; i++)
        #pragma unroll
        for (int j = 0; j < 4; j++)
            #pragma unroll
            for (int e = 0; e < 4; e++) acc[i][j][e] = 0.f;

    const int la_k = tid & 15, la_r = tid >> 4;

    for (int kb = 0; kb < K; kb += 16) {
        #pragma unroll
        for (int it = 0; it < 8; it++) {
            int r = la_r + it * 16;
            float va = A[(long)(m0 + r) * lda + kb + la_k];
            __nv_bfloat16 hi = __float2bfloat16(va);
            __nv_bfloat16 lo = __float2bfloat16(va - __bfloat162float(hi));
            sA[r * ST + 3 * la_k]     = hi;
            sA[r * ST + 3 * la_k + 1] = lo;
            sA[r * ST + 3 * la_k + 2] = hi;
            float vb = B[(long)(n0 + r) * ldb + kb + la_k];
            hi = __float2bfloat16(vb);
            lo = __float2bfloat16(vb - __bfloat162float(hi));
            sB[r * ST + 3 * la_k]     = hi;
            sB[r * ST + 3 * la_k + 1] = hi;
            sB[r * ST + 3 * la_k + 2] = lo;
        }
        __syncthreads();
        #pragma unroll
        for (int ks = 0; ks < 3; ks++) {
            const int kk0 = ks * 16;
            uint32_t af[4][4], bf[4][2];
            #pragma unroll
            for (int i = 0; i < 4; i++) {
                int ra = wm * 64 + i * 16 + tg;
                af[i][0] = *(const uint32_t*)&sA[(ra    ) * ST + kk0 + tk    ];
                af[i][1] = *(const uint32_t*)&sA[(ra + 8) * ST + kk0 + tk    ];
                af[i][2] = *(const uint32_t*)&sA[(ra    ) * ST + kk0 + tk + 8];
                af[i][3] = *(const uint32_t*)&sA[(ra + 8) * ST + kk0 + tk + 8];
            }
            #pragma unroll
            for (int j = 0; j < 4; j++) {
                int rb = wn * 32 + j * 8 + tg;
                bf[j][0] = *(const uint32_t*)&sB[rb * ST + kk0 + tk    ];
                bf[j][1] = *(const uint32_t*)&sB[rb * ST + kk0 + tk + 8];
            }
            #pragma unroll
            for (int i = 0; i < 4; i++)
                #pragma unroll
                for (int j = 0; j < 4; j++)
                    mma16816(acc[i][j], af[i][0], af[i][1], af[i][2], af[i][3], bf[j][0], bf[j][1]);
        }
        __syncthreads();
    }

    const int gr = tg, gc = tk;
    #pragma unroll
    for (int i = 0; i < 4; i++) {
        #pragma unroll
        for (int j = 0; j < 4; j++) {
            int rbase = m0 + wm * 64 + i * 16 + gr;
            int cbase = n0 + wn * 32 + j * 8 + gc;
            #pragma unroll
            for (int e = 0; e < 4; e++) {
                int r = rbase + (e >> 1) * 8;
                int c = cbase + (e & 1);
                float v = acc[i][j][e];
                if (EPI == 0) {
                    outb[(long)z * TT * TT + (long)r * TT + c] = v * 0.08838834764831845f;
                } else {
                    int b = z >> 4, h = z & 15;
                    outb[((long)(b * TT + r)) * D_MODEL + h * DH + c] = v;
                }
            }
        }
    }
}

// ---------------- reductions ----------------
__device__ __forceinline__ float warp_sum(float v) {
    #pragma unroll
    for (int o = 16; o; o >>= 1) v += __shfl_xor_sync(0xffffffffu, v, o);
    return v;
}
__device__ __forceinline__ float warp_max(float v) {
    #pragma unroll
    for (int o = 16; o; o >>= 1) v = fmaxf(v, __shfl_xor_sync(0xffffffffu, v, o));
    return v;
}
template<int NW>
__device__ __forceinline__ float block_sum(float v, float* buf) {
    int tid = threadIdx.x;
    v = warp_sum(v);
    __syncthreads();
    if ((tid & 31) == 0) buf[tid >> 5] = v;
    __syncthreads();
    if (tid == 0) { float t = 0; for (int i = 0; i < NW; i++) t += buf[i]; buf[0] = t; }
    __syncthreads();
    return buf[0];
}
template<int NW>
__device__ __forceinline__ float block_max(float v, float* buf) {
    int tid = threadIdx.x;
    v = warp_max(v);
    __syncthreads();
    if ((tid & 31) == 0) buf[tid >> 5] = v;
    __syncthreads();
    if (tid == 0) { float t = buf[0]; for (int i = 1; i < NW; i++) t = fmaxf(t, buf[i]); buf[0] = t; }
    __syncthreads();
    return buf[0];
}

// ------- LN (optional) + Hadamard-2048 -> fp16, one block/token -------
template<bool DO_LN>
__global__ void __launch_bounds__(256) ln_had2048(
    const float* __restrict__ in, const float* __restrict__ g,
    const float* __restrict__ bta, __half* __restrict__ outs)
{
    __shared__ float s[2048];
    __shared__ float red[8];
    const int tid = threadIdx.x;
    const float* x = in + (long)blockIdx.x * 2048;
    float loc[8];
    #pragma unroll
    for (int j = 0; j < 8; j++) loc[j] = x[tid + 256 * j];

    if (DO_LN) {
        float sm = 0.f, sq = 0.f;
        #pragma unroll
        for (int j = 0; j < 8; j++) { sm += loc[j]; sq += loc[j] * loc[j]; }
        float S  = block_sum<8>(sm, red);
        float SQ = block_sum<8>(sq, red);
        float mu = S * (1.0f / 2048.0f);
        float var = SQ * (1.0f / 2048.0f) - mu * mu;
        float inv = rsqrtf(var + 1e-5f);
        #pragma unroll
        for (int j = 0; j < 8; j++) {
            int c = tid + 256 * j;
            loc[j] = (loc[j] - mu) * inv * g[c] + bta[c];
        }
    }
    #pragma unroll
    for (int j = 0; j < 8; j++) s[tid + 256 * j] = loc[j];

    int sh = 0;
    for (int h = 1; h < 2048; h <<= 1, sh++) {
        __syncthreads();
        #pragma unroll
        for (int j = 0; j < 4; j++) {
            int pi = tid + 256 * j;
            int idx = ((pi >> sh) << (sh + 1)) + (pi & (h - 1));
            float a = s[idx], c = s[idx + h];
            s[idx] = a + c;
            s[idx + h] = a - c;
        }
    }
    __syncthreads();
    __half* o = outs + (long)blockIdx.x * 2048;
    #pragma unroll
    for (int j = 0; j < 8; j++) {
        int c = tid + 256 * j;
        o[c] = __float2half_rn(s[c] * 0.022097086912079608f);
    }
}

// ------- GELU(exact) + Hadamard-8192 -> fp16, one block/token -------
__global__ void __launch_bounds__(512) gelu_had8192(const float* __restrict__ in, __half* __restrict__ outs)
{
    __shared__ float s[8192];
    const int tid = threadIdx.x;
    const float* x = in + (long)blockIdx.x * 8192;
    #pragma unroll
    for (int j = 0; j < 16; j++) {
        float v = x[tid + 512 * j];
        v = 0.5f * v * (1.0f + erff(v * 0.7071067811865476f));
        s[tid + 512 * j] = v;
    }
    int sh = 0;
    for (int h = 1; h < 8192; h <<= 1, sh++) {
        __syncthreads();
        #pragma unroll
        for (int j = 0; j < 8; j++) {
            int pi = tid + 512 * j;
            int idx = ((pi >> sh) << (sh + 1)) + (pi & (h - 1));
            float a = s[idx], c = s[idx + h];
            s[idx] = a + c;
            s[idx + h] = a - c;
        }
    }
    __syncthreads();
    __half* o = outs + (long)blockIdx.x * 8192;
    #pragma unroll
    for (int j = 0; j < 16; j++) {
        int c = tid + 512 * j;
        o[c] = __float2half_rn(s[c] * 0.011048543456039806f);
    }
}

// ---------------- softmax over rows of 1024 (in-place) ----------------
__global__ void __launch_bounds__(256) softmax1024(float* __restrict__ sc)
{
    __shared__ float red[8];
    const int tid = threadIdx.x;
    float* row = sc + (long)blockIdx.x * 1024;
    float v[4];
    float mx = -3.4e38f;
    #pragma unroll
    for (int j = 0; j < 4; j++) { v[j] = row[tid + 256 * j]; mx = fmaxf(mx, v[j]); }
    float m = block_max<8>(mx, red);
    float sm = 0.f;
    #pragma unroll
    for (int j = 0; j < 4; j++) { v[j] = __expf(v[j] - m); sm += v[j]; }
    float S = block_sum<8>(sm, red);
    float inv = 1.0f / S;
    #pragma unroll
    for (int j = 0; j < 4; j++) row[tid + 256 * j] = v[j] * inv;
}

// ============================================================================
extern "C" void kernel_launch(void* const* d_in, const int* in_sizes, int n_in,
                              void* d_out, int out_size)
{
    const float*  x    = (const float*) d_in[0];
    const float*  ln1g = (const float*) d_in[1];
    const float*  ln1b = (const float*) d_in[2];
    const float*  ln2g = (const float*) d_in[3];
    const float*  ln2b = (const float*) d_in[4];
    const void*   Qq   = d_in[5];
    const float*  sq   = (const float*) d_in[6];
    const void*   Qk   = d_in[7];
    const float*  sk   = (const float*) d_in[8];
    const void*   Qv   = d_in[9];
    const float*  sv   = (const float*) d_in[10];
    const void*   Qo   = d_in[11];
    const float*  so   = (const float*) d_in[12];
    const void*   Qf1  = d_in[13];
    const float*  sf1  = (const float*) d_in[14];
    const float*  bf1  = (const float*) d_in[15];
    const void*   Qf2  = d_in[16];
    const float*  sf2  = (const float*) d_in[17];
    const float*  bf2  = (const float*) d_in[18];
    float* out = (float*)d_out;

    float *q, *k, *vt, *sc, *at, *x1, *ff;
    __half *hd, *hf, *wb;
    cudaGetSymbolAddress((void**)&q,   g_q);
    cudaGetSymbolAddress((void**)&k,   g_k);
    cudaGetSymbolAddress((void**)&vt,  g_vt);
    cudaGetSymbolAddress((void**)&sc,  g_sc);
    cudaGetSymbolAddress((void**)&at,  g_at);
    cudaGetSymbolAddress((void**)&x1,  g_x1);
    cudaGetSymbolAddress((void**)&ff,  g_ff);
    cudaGetSymbolAddress((void**)&hd,  g_hd);
    cudaGetSymbolAddress((void**)&hf,  g_hf);
    cudaGetSymbolAddress((void**)&wb,  g_w);

    __half* wq  = wb;
    __half* wk  = wb + NWD;
    __half* wv  = wb + 2 * NWD;
    __half* wo  = wb + 3 * NWD;
    __half* wf1 = wb + 4 * NWD;
    __half* wf2 = wb + 4 * NWD + NWF;

    cudaFuncSetAttribute((const void*)gemm_h<1, false, false>, cudaFuncAttributeMaxDynamicSharedMemorySize, SMEM_H);
    cudaFuncSetAttribute((const void*)gemm_h<2, false, false>, cudaFuncAttributeMaxDynamicSharedMemorySize, SMEM_H);
    cudaFuncSetAttribute((const void*)gemm_h<0, false, true>,  cudaFuncAttributeMaxDynamicSharedMemorySize, SMEM_H);
    cudaFuncSetAttribute((const void*)gemm_h<0, true, false>,  cudaFuncAttributeMaxDynamicSharedMemorySize, SMEM_H);
    cudaFuncSetAttribute((const void*)gemm_h<0, true, true>,   cudaFuncAttributeMaxDynamicSharedMemorySize, SMEM_H);

    // 0. dtype probe + normalize weights to fp16 (exact for int8 values)
    zero_counters<<<1, 1>>>();
    probe_dtype<<<4096, 256>>>(Qq, 1 << 20);
    convert_w<<<(int)((NWD + 255) / 256), 256>>>(Qq,  wq,  NWD);
    convert_w<<<(int)((NWD + 255) / 256), 256>>>(Qk,  wk,  NWD);
    convert_w<<<(int)((NWD + 255) / 256), 256>>>(Qv,  wv,  NWD);
    convert_w<<<(int)((NWD + 255) / 256), 256>>>(Qo,  wo,  NWD);
    convert_w<<<(int)((NWF + 255) / 256), 256>>>(Qf1, wf1, NWF);
    convert_w<<<(int)((NWF + 255) / 256), 256>>>(Qf2, wf2, NWF);

    // 1. LN1 + Hadamard -> fp16
    ln_had2048<true><<<BT, 256>>>(x, ln1g, ln1b, hd);
    // 2-4. Q/K/V projections (fp16 HMMA)
    gemm_h<1, false, false><<<dim3(16, 32), 256, SMEM_H>>>(hd, wq, D_MODEL, sq, nullptr, nullptr, q,  0);
    gemm_h<1, false, false><<<dim3(16, 32), 256, SMEM_H>>>(hd, wk, D_MODEL, sk, nullptr, nullptr, k,  0);
    gemm_h<2, false, false><<<dim3(16, 32), 256, SMEM_H>>>(hd, wv, D_MODEL, sv, nullptr, nullptr, vt, 0);
    // 5. scores = q @ k^T / sqrt(128)
    gemm_p<0><<<dim3(8, 8, BH), 256>>>(q, k, sc, DH, DH, DH, (long)TT * DH, (long)TT * DH);
    // 6. softmax
    softmax1024<<<BH * TT, 256>>>(sc);
    // 7. attn = P @ V
    gemm_p<1><<<dim3(1, 8, BH), 256>>>(sc, vt, at, TT, TT, TT, (long)TT * TT, (long)DH * TT);
    // 8. Hadamard(attn) -> fp16
    ln_had2048<false><<<BT, 256>>>(at, nullptr, nullptr, hd);
    // 9. x1 = x + O-proj
    gemm_h<0, false, true><<<dim3(16, 32), 256, SMEM_H>>>(hd, wo, D_MODEL, so, nullptr, x, x1, D_MODEL);
    // 10. LN2 + Hadamard -> fp16
    ln_had2048<true><<<BT, 256>>>(x1, ln2g, ln2b, hd);
    // 11. FF1 (+bias)
    gemm_h<0, true, false><<<dim3(64, 32), 256, SMEM_H>>>(hd, wf1, D_MODEL, sf1, bf1, nullptr, ff, D_FF);
    // 12. GELU + Hadamard-8192 -> fp16
    gelu_had8192<<<BT, 512>>>(ff, hf);
    // 13. out = x1 + FF2 (+bias)
    gemm_h<0, true, true><<<dim3(16, 32), 256, SMEM_H>>>(hf, wf2, D_FF, sf2, bf2, x1, out, D_MODEL);
}

// round 8
// speedup vs baseline: 4.0434x; 1.2224x over previous
#include <cuda_runtime.h>
#include <cuda_bf16.h>
#include <cuda_fp16.h>
#include <cstdint>

#define D_MODEL 2048
#define N_HEADS 16
#define D_FF    8192
#define BB      4
#define TT      1024
#define BT      (BB*TT)      // 4096 tokens
#define DH      128
#define BH      (BB*N_HEADS) // 64

// ---------------- scratch (device globals; no allocs allowed) ----------------
__device__ float g_sc [(long)BH*TT*TT];     // scores fp32
__device__ float g_at [(long)BT*D_MODEL];   // attention output [b,t,h*d]
__device__ float g_x1 [(long)BT*D_MODEL];   // residual after O proj
__device__ float g_ff [(long)BT*D_FF];

// fp16 tensors
__device__ __align__(16) __half g_hd [(long)BT*D_MODEL];   // activations (d_model)
__device__ __align__(16) __half g_hf [(long)BT*D_FF];      // activations (d_ff)
__device__ __align__(16) __half g_qh [(long)BT*D_MODEL];   // q [b,h,t,d]
__device__ __align__(16) __half g_kh [(long)BT*D_MODEL];   // k [b,h,t,d]
__device__ __align__(16) __half g_vth[(long)BT*D_MODEL];   // v [b,h,d,t]
__device__ __align__(16) __half g_ph [(long)BH*TT*TT];     // probs fp16

// fp16 weights (int8 values exact in fp16)
#define NWD ((long)D_MODEL*D_MODEL)   // 4,194,304
#define NWF ((long)D_FF*D_MODEL)      // 16,777,216
__device__ __align__(16) __half g_w[(long)4*NWD + 2*NWF];
__device__ int g_cnt32;
__device__ int g_cntf;

// ---------------- dtype probe + weight normalization ----------------
__global__ void zero_counters() { g_cnt32 = 0; g_cntf = 0; }

__global__ void probe_dtype(const void* __restrict__ p, int nwords)
{
    int i = blockIdx.x * blockDim.x + threadIdx.x;
    if (i >= nwords) return;
    int v = ((const int*)p)[i];
    if (v < -127 || v > 127) atomicAdd(&g_cnt32, 1);
    float f = ((const float*)p)[i];
    bool okf = (f >= -127.0f) && (f <= 127.0f) && (f == rintf(f));
    if (!okf) atomicAdd(&g_cntf, 1);
}

__global__ void convert_w(const void* __restrict__ src, __half* __restrict__ dst, long n)
{
    long i = (long)blockIdx.x * blockDim.x + threadIdx.x;
    if (i >= n) return;
    int mode = (g_cnt32 == 0) ? 1 : ((g_cntf == 0) ? 2 : 0);  // 1=int32, 2=float32, 0=int8
    signed char v;
    if (mode == 1)      v = (signed char)((const int*)src)[i];
    else if (mode == 2) v = (signed char)__float2int_rn(((const float*)src)[i]);
    else                v = ((const signed char*)src)[i];
    dst[i] = __float2half_rn((float)v);
}

// ---------------- mma / ldmatrix / cp.async helpers ----------------
__device__ __forceinline__ void ldsm_x4(uint32_t& r0, uint32_t& r1, uint32_t& r2, uint32_t& r3, uint32_t a) {
    asm volatile("ldmatrix.sync.aligned.m8n8.x4.shared.b16 {%0,%1,%2,%3},[%4];"
                 : "=r"(r0), "=r"(r1), "=r"(r2), "=r"(r3) : "r"(a));
}
__device__ __forceinline__ void ldsm_x2(uint32_t& r0, uint32_t& r1, uint32_t a) {
    asm volatile("ldmatrix.sync.aligned.m8n8.x2.shared.b16 {%0,%1},[%2];"
                 : "=r"(r0), "=r"(r1) : "r"(a));
}
__device__ __forceinline__ void mma16816h(float* c, uint32_t a0, uint32_t a1, uint32_t a2, uint32_t a3,
                                          uint32_t b0, uint32_t b1) {
    asm volatile("mma.sync.aligned.m16n8k16.row.col.f32.f16.f16.f32 "
                 "{%0,%1,%2,%3},{%4,%5,%6,%7},{%8,%9},{%0,%1,%2,%3};"
                 : "+f"(c[0]), "+f"(c[1]), "+f"(c[2]), "+f"(c[3])
                 : "r"(a0), "r"(a1), "r"(a2), "r"(a3), "r"(b0), "r"(b1));
}
__device__ __forceinline__ void cp16(uint32_t dst, const void* src) {
    asm volatile("cp.async.cg.shared.global [%0], [%1], 16;"
                 :: "r"(dst), "l"(__cvta_generic_to_global(src)) : "memory");
}
__device__ __forceinline__ uint32_t smem_u32(const void* p) {
    uint32_t a;
    asm("{ .reg .u64 t; cvta.to.shared.u64 t, %1; cvt.u32.u64 %0, t; }" : "=r"(a) : "l"(p));
    return a;
}

#define HST 32768                     // bytes per stage (A 16K + B 16K)
#define SH_A(s) ((s)*HST)
#define SH_B(s) ((s)*HST + 16384)
#define SMEM_H  (3*HST)               // 98304 bytes

// ============================================================================
// GEMM-H (fp16, cp.async 3-stage pipeline): weight GEMMs
//   C[M=4096, N] = A[M, K] @ W[N, K]^T  then *s[col] (+bias) (+res)
// LAYOUT: 0 = fp32 out[r*ldc+c], 1 = fp16 q/k head layout, 2 = fp16 V^T layout
// ============================================================================
template<int LAYOUT, bool HAS_BIAS, bool HAS_RES>
__global__ void __launch_bounds__(256) gemm_h(
    const __half* __restrict__ A, const __half* __restrict__ W, int K,
    const float* __restrict__ s, const float* __restrict__ bias,
    const float* __restrict__ res, void* __restrict__ outp, int ldc)
{
    extern __shared__ char smem[];
    const uint32_t sb = smem_u32(smem);
    const int tid = threadIdx.x, lane = tid & 31, w = tid >> 5;
    const int wm = w & 1, wn = w >> 1;           // warp grid 2(M) x 4(N)
    const int m0 = blockIdx.y * 128, n0 = blockIdx.x * 128;
    const int KB = K >> 6;

    const __half* Ag = A + (long)m0 * K;
    const __half* Bg = W + (long)n0 * K;

    const int lr = tid >> 3, lj = tid & 7;

    auto load_stage = [&](int st, int kb) {
        const __half* a = Ag + kb * 64;
        const __half* b = Bg + kb * 64;
        #pragma unroll
        for (int i = 0; i < 4; i++) {
            int r = lr + i * 32;
            uint32_t dsw = r * 128 + ((lj ^ (r & 7)) * 16);
            cp16(sb + SH_A(st) + dsw, a + (long)r * K + lj * 8);
        }
        #pragma unroll
        for (int i = 0; i < 4; i++) {
            int r = lr + i * 32;
            uint32_t dsw = r * 128 + ((lj ^ (r & 7)) * 16);
            cp16(sb + SH_B(st) + dsw, b + (long)r * K + lj * 8);
        }
        asm volatile("cp.async.commit_group;" ::: "memory");
    };

    float acc[4][4][4];
    #pragma unroll
    for (int i = 0; i < 4; i++)
        #pragma unroll
        for (int j = 0; j < 4; j++)
            #pragma unroll
            for (int e = 0; e < 4; e++) acc[i][j][e] = 0.f;

    load_stage(0, 0);
    if (KB > 1) load_stage(1, 1);

    for (int kb = 0; kb < KB; kb++) {
        const int st = kb % 3;
        if (kb + 1 < KB) { asm volatile("cp.async.wait_group 1;" ::: "memory"); }
        else             { asm volatile("cp.async.wait_group 0;" ::: "memory"); }
        __syncthreads();
        if (kb + 2 < KB) load_stage((kb + 2) % 3, kb + 2);

        const uint32_t aB = sb + SH_A(st), bB = sb + SH_B(st);
        #pragma unroll
        for (int ks = 0; ks < 4; ks++) {
            const int kk0 = ks * 16;
            uint32_t af[4][4], bf[4][2];
            #pragma unroll
            for (int i = 0; i < 4; i++) {
                int ra = wm * 64 + i * 16 + (lane & 15);
                int kk = kk0 + (lane >> 4) * 8;
                uint32_t ad = aB + ra * 128 + (((kk >> 3) ^ (ra & 7)) * 16);
                ldsm_x4(af[i][0], af[i][1], af[i][2], af[i][3], ad);
            }
            #pragma unroll
            for (int j = 0; j < 4; j++) {
                int rb = wn * 32 + j * 8 + (lane & 7);
                int kk = kk0 + ((lane >> 3) & 1) * 8;
                uint32_t bd = bB + rb * 128 + (((kk >> 3) ^ (rb & 7)) * 16);
                ldsm_x2(bf[j][0], bf[j][1], bd);
            }
            #pragma unroll
            for (int i = 0; i < 4; i++)
                #pragma unroll
                for (int j = 0; j < 4; j++)
                    mma16816h(acc[i][j], af[i][0], af[i][1], af[i][2], af[i][3], bf[j][0], bf[j][1]);
        }
    }

    // --- epilogue ---
    const int gr = lane >> 2, gc = (lane & 3) * 2;
    #pragma unroll
    for (int i = 0; i < 4; i++) {
        #pragma unroll
        for (int j = 0; j < 4; j++) {
            int rbase = m0 + wm * 64 + i * 16 + gr;
            int cbase = n0 + wn * 32 + j * 8 + gc;
            #pragma unroll
            for (int e = 0; e < 4; e++) {
                int r = rbase + (e >> 1) * 8;
                int c = cbase + (e & 1);
                float v = acc[i][j][e] * s[c];
                if (HAS_BIAS) v += bias[c];
                if (HAS_RES)  v += res[(long)r * D_MODEL + c];
                if (LAYOUT == 0) {
                    ((float*)outp)[(long)r * ldc + c] = v;
                } else {
                    int b = r >> 10, t = r & 1023, h = c >> 7, d = c & 127;
                    long idx;
                    if (LAYOUT == 1) idx = (long)(b * N_HEADS + h) * (TT * DH) + (long)t * DH + d;
                    else             idx = (long)(b * N_HEADS + h) * (TT * DH) + (long)d * TT + t;
                    ((__half*)outp)[idx] = __float2half_rn(v);
                }
            }
        }
    }
}

// ============================================================================
// GEMM-A (fp16 batched, cp.async 3-stage pipeline): attention GEMMs
//   C[z][M,N] = A[z][M,K] @ B[z][N,K]^T
// EPI 0: scores -> fp32 * 1/sqrt(128) at sc[z][r][c]
// EPI 1: P@V    -> fp32 at[(b*TT+r)*D_MODEL + h*DH + c],  b=z>>4, h=z&15
// ============================================================================
template<int EPI>
__global__ void __launch_bounds__(256) gemm_a(
    const __half* __restrict__ Ab, const __half* __restrict__ Bb,
    float* __restrict__ outb, int K, long sAz, long sBz)
{
    extern __shared__ char smem[];
    const uint32_t sb = smem_u32(smem);
    const int tid = threadIdx.x, lane = tid & 31, w = tid >> 5;
    const int wm = w & 1, wn = w >> 1;
    const int z = blockIdx.z;
    const int m0 = blockIdx.y * 128, n0 = blockIdx.x * 128;
    const int KB = K >> 6;

    const __half* Ag = Ab + (long)z * sAz + (long)m0 * K;
    const __half* Bg = Bb + (long)z * sBz + (long)n0 * K;

    const int lr = tid >> 3, lj = tid & 7;

    auto load_stage = [&](int st, int kb) {
        const __half* a = Ag + kb * 64;
        const __half* b = Bg + kb * 64;
        #pragma unroll
        for (int i = 0; i < 4; i++) {
            int r = lr + i * 32;
            uint32_t dsw = r * 128 + ((lj ^ (r & 7)) * 16);
            cp16(sb + SH_A(st) + dsw, a + (long)r * K + lj * 8);
        }
        #pragma unroll
        for (int i = 0; i < 4; i++) {
            int r = lr + i * 32;
            uint32_t dsw = r * 128 + ((lj ^ (r & 7)) * 16);
            cp16(sb + SH_B(st) + dsw, b + (long)r * K + lj * 8);
        }
        asm volatile("cp.async.commit_group;" ::: "memory");
    };

    float acc[4][4][4];
    #pragma unroll
    for (int i = 0; i < 4; i++)
        #pragma unroll
        for (int j = 0; j < 4; j++)
            #pragma unroll
            for (int e = 0; e < 4; e++) acc[i][j][e] = 0.f;

    load_stage(0, 0);
    if (KB > 1) load_stage(1, 1);

    for (int kb = 0; kb < KB; kb++) {
        const int st = kb % 3;
        if (kb + 1 < KB) { asm volatile("cp.async.wait_group 1;" ::: "memory"); }
        else             { asm volatile("cp.async.wait_group 0;" ::: "memory"); }
        __syncthreads();
        if (kb + 2 < KB) load_stage((kb + 2) % 3, kb + 2);

        const uint32_t aB = sb + SH_A(st), bB = sb + SH_B(st);
        #pragma unroll
        for (int ks = 0; ks < 4; ks++) {
            const int kk0 = ks * 16;
            uint32_t af[4][4], bf[4][2];
            #pragma unroll
            for (int i = 0; i < 4; i++) {
                int ra = wm * 64 + i * 16 + (lane & 15);
                int kk = kk0 + (lane >> 4) * 8;
                uint32_t ad = aB + ra * 128 + (((kk >> 3) ^ (ra & 7)) * 16);
                ldsm_x4(af[i][0], af[i][1], af[i][2], af[i][3], ad);
            }
            #pragma unroll
            for (int j = 0; j < 4; j++) {
                int rb = wn * 32 + j * 8 + (lane & 7);
                int kk = kk0 + ((lane >> 3) & 1) * 8;
                uint32_t bd = bB + rb * 128 + (((kk >> 3) ^ (rb & 7)) * 16);
                ldsm_x2(bf[j][0], bf[j][1], bd);
            }
            #pragma unroll
            for (int i = 0; i < 4; i++)
                #pragma unroll
                for (int j = 0; j < 4; j++)
                    mma16816h(acc[i][j], af[i][0], af[i][1], af[i][2], af[i][3], bf[j][0], bf[j][1]);
        }
    }

    const int gr = lane >> 2, gc = (lane & 3) * 2;
    #pragma unroll
    for (int i = 0; i < 4; i++) {
        #pragma unroll
        for (int j = 0; j < 4; j++) {
            int rbase = m0 + wm * 64 + i * 16 + gr;
            int cbase = n0 + wn * 32 + j * 8 + gc;
            #pragma unroll
            for (int e = 0; e < 4; e++) {
                int r = rbase + (e >> 1) * 8;
                int c = cbase + (e & 1);
                float v = acc[i][j][e];
                if (EPI == 0) {
                    outb[(long)z * TT * TT + (long)r * TT + c] = v * 0.08838834764831845f;
                } else {
                    int b = z >> 4, h = z & 15;
                    outb[((long)(b * TT + r)) * D_MODEL + h * DH + c] = v;
                }
            }
        }
    }
}

// ---------------- reductions ----------------
__device__ __forceinline__ float warp_sum(float v) {
    #pragma unroll
    for (int o = 16; o; o >>= 1) v += __shfl_xor_sync(0xffffffffu, v, o);
    return v;
}
__device__ __forceinline__ float warp_max(float v) {
    #pragma unroll
    for (int o = 16; o; o >>= 1) v = fmaxf(v, __shfl_xor_sync(0xffffffffu, v, o));
    return v;
}
template<int NW>
__device__ __forceinline__ float block_sum(float v, float* buf) {
    int tid = threadIdx.x;
    v = warp_sum(v);
    __syncthreads();
    if ((tid & 31) == 0) buf[tid >> 5] = v;
    __syncthreads();
    if (tid == 0) { float t = 0; for (int i = 0; i < NW; i++) t += buf[i]; buf[0] = t; }
    __syncthreads();
    return buf[0];
}
template<int NW>
__device__ __forceinline__ float block_max(float v, float* buf) {
    int tid = threadIdx.x;
    v = warp_max(v);
    __syncthreads();
    if ((tid & 31) == 0) buf[tid >> 5] = v;
    __syncthreads();
    if (tid == 0) { float t = buf[0]; for (int i = 1; i < NW; i++) t = fmaxf(t, buf[i]); buf[0] = t; }
    __syncthreads();
    return buf[0];
}

// ------- LN (optional) + Hadamard-2048 -> fp16, one block/token -------
template<bool DO_LN>
__global__ void __launch_bounds__(256) ln_had2048(
    const float* __restrict__ in, const float* __restrict__ g,
    const float* __restrict__ bta, __half* __restrict__ outs)
{
    __shared__ float s[2048];
    __shared__ float red[8];
    const int tid = threadIdx.x;
    const float* x = in + (long)blockIdx.x * 2048;
    float loc[8];
    #pragma unroll
    for (int j = 0; j < 8; j++) loc[j] = x[tid + 256 * j];

    if (DO_LN) {
        float sm = 0.f, sq = 0.f;
        #pragma unroll
        for (int j = 0; j < 8; j++) { sm += loc[j]; sq += loc[j] * loc[j]; }
        float S  = block_sum<8>(sm, red);
        float SQ = block_sum<8>(sq, red);
        float mu = S * (1.0f / 2048.0f);
        float var = SQ * (1.0f / 2048.0f) - mu * mu;
        float inv = rsqrtf(var + 1e-5f);
        #pragma unroll
        for (int j = 0; j < 8; j++) {
            int c = tid + 256 * j;
            loc[j] = (loc[j] - mu) * inv * g[c] + bta[c];
        }
    }
    #pragma unroll
    for (int j = 0; j < 8; j++) s[tid + 256 * j] = loc[j];

    int sh = 0;
    for (int h = 1; h < 2048; h <<= 1, sh++) {
        __syncthreads();
        #pragma unroll
        for (int j = 0; j < 4; j++) {
            int pi = tid + 256 * j;
            int idx = ((pi >> sh) << (sh + 1)) + (pi & (h - 1));
            float a = s[idx], c = s[idx + h];
            s[idx] = a + c;
            s[idx + h] = a - c;
        }
    }
    __syncthreads();
    __half* o = outs + (long)blockIdx.x * 2048;
    #pragma unroll
    for (int j = 0; j < 8; j++) {
        int c = tid + 256 * j;
        o[c] = __float2half_rn(s[c] * 0.022097086912079608f);
    }
}

// ------- GELU(exact) + Hadamard-8192 -> fp16, one block/token -------
__global__ void __launch_bounds__(512) gelu_had8192(const float* __restrict__ in, __half* __restrict__ outs)
{
    __shared__ float s[8192];
    const int tid = threadIdx.x;
    const float* x = in + (long)blockIdx.x * 8192;
    #pragma unroll
    for (int j = 0; j < 16; j++) {
        float v = x[tid + 512 * j];
        v = 0.5f * v * (1.0f + erff(v * 0.7071067811865476f));
        s[tid + 512 * j] = v;
    }
    int sh = 0;
    for (int h = 1; h < 8192; h <<= 1, sh++) {
        __syncthreads();
        #pragma unroll
        for (int j = 0; j < 8; j++) {
            int pi = tid + 512 * j;
            int idx = ((pi >> sh) << (sh + 1)) + (pi & (h - 1));
            float a = s[idx], c = s[idx + h];
            s[idx] = a + c;
            s[idx + h] = a - c;
        }
    }
    __syncthreads();
    __half* o = outs + (long)blockIdx.x * 8192;
    #pragma unroll
    for (int j = 0; j < 16; j++) {
        int c = tid + 512 * j;
        o[c] = __float2half_rn(s[c] * 0.011048543456039806f);
    }
}

// ------ softmax over rows of 1024: fp32 scores in -> fp16 probs out ------
__global__ void __launch_bounds__(256) softmax1024(const float* __restrict__ sc, __half* __restrict__ pout)
{
    __shared__ float red[8];
    const int tid = threadIdx.x;
    const float* row = sc + (long)blockIdx.x * 1024;
    __half* orow = pout + (long)blockIdx.x * 1024;
    float v[4];
    float mx = -3.4e38f;
    #pragma unroll
    for (int j = 0; j < 4; j++) { v[j] = row[tid + 256 * j]; mx = fmaxf(mx, v[j]); }
    float m = block_max<8>(mx, red);
    float sm = 0.f;
    #pragma unroll
    for (int j = 0; j < 4; j++) { v[j] = __expf(v[j] - m); sm += v[j]; }
    float S = block_sum<8>(sm, red);
    float inv = 1.0f / S;
    #pragma unroll
    for (int j = 0; j < 4; j++) orow[tid + 256 * j] = __float2half_rn(v[j] * inv);
}

// ============================================================================
extern "C" void kernel_launch(void* const* d_in, const int* in_sizes, int n_in,
                              void* d_out, int out_size)
{
    const float*  x    = (const float*) d_in[0];
    const float*  ln1g = (const float*) d_in[1];
    const float*  ln1b = (const float*) d_in[2];
    const float*  ln2g = (const float*) d_in[3];
    const float*  ln2b = (const float*) d_in[4];
    const void*   Qq   = d_in[5];
    const float*  sq   = (const float*) d_in[6];
    const void*   Qk   = d_in[7];
    const float*  sk   = (const float*) d_in[8];
    const void*   Qv   = d_in[9];
    const float*  sv   = (const float*) d_in[10];
    const void*   Qo   = d_in[11];
    const float*  so   = (const float*) d_in[12];
    const void*   Qf1  = d_in[13];
    const float*  sf1  = (const float*) d_in[14];
    const float*  bf1  = (const float*) d_in[15];
    const void*   Qf2  = d_in[16];
    const float*  sf2  = (const float*) d_in[17];
    const float*  bf2  = (const float*) d_in[18];
    float* out = (float*)d_out;

    float *sc, *at, *x1, *ff;
    __half *hd, *hf, *qh, *kh, *vth, *ph, *wb;
    cudaGetSymbolAddress((void**)&sc,  g_sc);
    cudaGetSymbolAddress((void**)&at,  g_at);
    cudaGetSymbolAddress((void**)&x1,  g_x1);
    cudaGetSymbolAddress((void**)&ff,  g_ff);
    cudaGetSymbolAddress((void**)&hd,  g_hd);
    cudaGetSymbolAddress((void**)&hf,  g_hf);
    cudaGetSymbolAddress((void**)&qh,  g_qh);
    cudaGetSymbolAddress((void**)&kh,  g_kh);
    cudaGetSymbolAddress((void**)&vth, g_vth);
    cudaGetSymbolAddress((void**)&ph,  g_ph);
    cudaGetSymbolAddress((void**)&wb,  g_w);

    __half* wq  = wb;
    __half* wk  = wb + NWD;
    __half* wv  = wb + 2 * NWD;
    __half* wo  = wb + 3 * NWD;
    __half* wf1 = wb + 4 * NWD;
    __half* wf2 = wb + 4 * NWD + NWF;

    cudaFuncSetAttribute((const void*)gemm_h<1, false, false>, cudaFuncAttributeMaxDynamicSharedMemorySize, SMEM_H);
    cudaFuncSetAttribute((const void*)gemm_h<2, false, false>, cudaFuncAttributeMaxDynamicSharedMemorySize, SMEM_H);
    cudaFuncSetAttribute((const void*)gemm_h<0, false, true>,  cudaFuncAttributeMaxDynamicSharedMemorySize, SMEM_H);
    cudaFuncSetAttribute((const void*)gemm_h<0, true, false>,  cudaFuncAttributeMaxDynamicSharedMemorySize, SMEM_H);
    cudaFuncSetAttribute((const void*)gemm_h<0, true, true>,   cudaFuncAttributeMaxDynamicSharedMemorySize, SMEM_H);
    cudaFuncSetAttribute((const void*)gemm_a<0>,               cudaFuncAttributeMaxDynamicSharedMemorySize, SMEM_H);
    cudaFuncSetAttribute((const void*)gemm_a<1>,               cudaFuncAttributeMaxDynamicSharedMemorySize, SMEM_H);

    // 0. dtype probe + normalize weights to fp16 (exact for int8 values)
    zero_counters<<<1, 1>>>();
    probe_dtype<<<4096, 256>>>(Qq, 1 << 20);
    convert_w<<<(int)((NWD + 255) / 256), 256>>>(Qq,  wq,  NWD);
    convert_w<<<(int)((NWD + 255) / 256), 256>>>(Qk,  wk,  NWD);
    convert_w<<<(int)((NWD + 255) / 256), 256>>>(Qv,  wv,  NWD);
    convert_w<<<(int)((NWD + 255) / 256), 256>>>(Qo,  wo,  NWD);
    convert_w<<<(int)((NWF + 255) / 256), 256>>>(Qf1, wf1, NWF);
    convert_w<<<(int)((NWF + 255) / 256), 256>>>(Qf2, wf2, NWF);

    // 1. LN1 + Hadamard -> fp16
    ln_had2048<true><<<BT, 256>>>(x, ln1g, ln1b, hd);
    // 2-4. Q/K/V projections -> fp16 head layouts
    gemm_h<1, false, false><<<dim3(16, 32), 256, SMEM_H>>>(hd, wq, D_MODEL, sq, nullptr, nullptr, qh,  0);
    gemm_h<1, false, false><<<dim3(16, 32), 256, SMEM_H>>>(hd, wk, D_MODEL, sk, nullptr, nullptr, kh,  0);
    gemm_h<2, false, false><<<dim3(16, 32), 256, SMEM_H>>>(hd, wv, D_MODEL, sv, nullptr, nullptr, vth, 0);
    // 5. scores = q @ k^T / sqrt(128)  (fp16 in, fp32 out)
    gemm_a<0><<<dim3(8, 8, BH), 256, SMEM_H>>>(qh, kh, sc, DH, (long)TT * DH, (long)TT * DH);
    // 6. softmax fp32 -> fp16 probs
    softmax1024<<<BH * TT, 256>>>(sc, ph);
    // 7. attn = P @ V  (fp16 in, fp32 out)
    gemm_a<1><<<dim3(1, 8, BH), 256, SMEM_H>>>(ph, vth, at, TT, (long)TT * TT, (long)DH * TT);
    // 8. Hadamard(attn) -> fp16
    ln_had2048<false><<<BT, 256>>>(at, nullptr, nullptr, hd);
    // 9. x1 = x + O-proj
    gemm_h<0, false, true><<<dim3(16, 32), 256, SMEM_H>>>(hd, wo, D_MODEL, so, nullptr, x, x1, D_MODEL);
    // 10. LN2 + Hadamard -> fp16
    ln_had2048<true><<<BT, 256>>>(x1, ln2g, ln2b, hd);
    // 11. FF1 (+bias)
    gemm_h<0, true, false><<<dim3(64, 32), 256, SMEM_H>>>(hd, wf1, D_MODEL, sf1, bf1, nullptr, ff, D_FF);
    // 12. GELU + Hadamard-8192 -> fp16
    gelu_had8192<<<BT, 512>>>(ff, hf);
    // 13. out = x1 + FF2 (+bias)
    gemm_h<0, true, true><<<dim3(16, 32), 256, SMEM_H>>>(hf, wf2, D_FF, sf2, bf2, x1, out, D_MODEL);
}

// round 9
// speedup vs baseline: 4.2984x; 1.0631x over previous
#include <cuda_runtime.h>
#include <cuda_bf16.h>
#include <cuda_fp16.h>
#include <cstdint>

#define D_MODEL 2048
#define N_HEADS 16
#define D_FF    8192
#define BB      4
#define TT      1024
#define BT      (BB*TT)      // 4096 tokens
#define DH      128
#define BH      (BB*N_HEADS) // 64

// ---------------- scratch (device globals; no allocs allowed) ----------------
__device__ float g_sc [(long)BH*TT*TT];     // scores fp32
__device__ float g_at [(long)BT*D_MODEL];   // attention output [b,t,h*d]
__device__ float g_x1 [(long)BT*D_MODEL];   // residual after O proj
__device__ float g_ff [(long)BT*D_FF];
__device__ float g_s6 [3*D_MODEL];          // concatenated q/k/v scales

// fp16 tensors
__device__ __align__(16) __half g_hd [(long)BT*D_MODEL];   // activations (d_model)
__device__ __align__(16) __half g_hf [(long)BT*D_FF];      // activations (d_ff)
__device__ __align__(16) __half g_qh [(long)BT*D_MODEL];   // q [b,h,t,d]
__device__ __align__(16) __half g_kh [(long)BT*D_MODEL];   // k [b,h,t,d]
__device__ __align__(16) __half g_vth[(long)BT*D_MODEL];   // v [b,h,d,t]
__device__ __align__(16) __half g_ph [(long)BH*TT*TT];     // probs fp16

// fp16 weights (int8 values exact in fp16); q,k,v contiguous for merged GEMM
#define NWD ((long)D_MODEL*D_MODEL)   // 4,194,304
#define NWF ((long)D_FF*D_MODEL)      // 16,777,216
__device__ __align__(16) __half g_w[(long)4*NWD + 2*NWF];
__device__ int g_cnt32;
__device__ int g_cntf;

// ---------------- dtype probe + weight normalization ----------------
__global__ void zero_counters() { g_cnt32 = 0; g_cntf = 0; }

__global__ void probe_dtype(const void* __restrict__ p, int nwords)
{
    int i = blockIdx.x * blockDim.x + threadIdx.x;
    if (i >= nwords) return;
    int v = ((const int*)p)[i];
    if (v < -127 || v > 127) atomicAdd(&g_cnt32, 1);
    float f = ((const float*)p)[i];
    bool okf = (f >= -127.0f) && (f <= 127.0f) && (f == rintf(f));
    if (!okf) atomicAdd(&g_cntf, 1);
}

__device__ __forceinline__ void conv4(const void* __restrict__ src, long j, __half2* __restrict__ dst2, long o)
{
    int mode = (g_cnt32 == 0) ? 1 : ((g_cntf == 0) ? 2 : 0);  // 1=int32, 2=float32, 0=int8
    float f0, f1, f2, f3;
    if (mode == 1) {
        int4 v = ((const int4*)src)[j];
        f0 = (float)v.x; f1 = (float)v.y; f2 = (float)v.z; f3 = (float)v.w;
    } else if (mode == 2) {
        float4 v = ((const float4*)src)[j];
        f0 = rintf(v.x); f1 = rintf(v.y); f2 = rintf(v.z); f3 = rintf(v.w);
    } else {
        char4 v = ((const char4*)src)[j];
        f0 = (float)v.x; f1 = (float)v.y; f2 = (float)v.z; f3 = (float)v.w;
    }
    dst2[2 * o]     = __floats2half2_rn(f0, f1);
    dst2[2 * o + 1] = __floats2half2_rn(f2, f3);
}

// vectorized single-matrix convert: n4 = n/4 quads
__global__ void convert_w4(const void* __restrict__ src, __half* __restrict__ dst, long n4)
{
    long i = (long)blockIdx.x * blockDim.x + threadIdx.x;
    if (i >= n4) return;
    conv4(src, i, (__half2*)dst, i);
}

// three matrices (q,k,v) -> contiguous dst; n4 quads each
__global__ void convert_w3(const void* __restrict__ s0, const void* __restrict__ s1,
                           const void* __restrict__ s2, __half* __restrict__ dst, long n4)
{
    long i = (long)blockIdx.x * blockDim.x + threadIdx.x;
    if (i >= 3 * n4) return;
    int which = (int)(i / n4);
    long j = i % n4;
    const void* src = (which == 0) ? s0 : ((which == 1) ? s1 : s2);
    conv4(src, j, (__half2*)dst, i);
}

__global__ void cat_scales(const float* __restrict__ a, const float* __restrict__ b,
                           const float* __restrict__ c, float* __restrict__ d)
{
    int i = blockIdx.x * blockDim.x + threadIdx.x;
    if (i >= 3 * D_MODEL) return;
    d[i] = (i < D_MODEL) ? a[i] : ((i < 2 * D_MODEL) ? b[i - D_MODEL] : c[i - 2 * D_MODEL]);
}

// ---------------- mma / ldmatrix / cp.async helpers ----------------
__device__ __forceinline__ void ldsm_x4(uint32_t& r0, uint32_t& r1, uint32_t& r2, uint32_t& r3, uint32_t a) {
    asm volatile("ldmatrix.sync.aligned.m8n8.x4.shared.b16 {%0,%1,%2,%3},[%4];"
                 : "=r"(r0), "=r"(r1), "=r"(r2), "=r"(r3) : "r"(a));
}
__device__ __forceinline__ void ldsm_x2(uint32_t& r0, uint32_t& r1, uint32_t a) {
    asm volatile("ldmatrix.sync.aligned.m8n8.x2.shared.b16 {%0,%1},[%2];"
                 : "=r"(r0), "=r"(r1) : "r"(a));
}
__device__ __forceinline__ void mma16816h(float* c, uint32_t a0, uint32_t a1, uint32_t a2, uint32_t a3,
                                          uint32_t b0, uint32_t b1) {
    asm volatile("mma.sync.aligned.m16n8k16.row.col.f32.f16.f16.f32 "
                 "{%0,%1,%2,%3},{%4,%5,%6,%7},{%8,%9},{%0,%1,%2,%3};"
                 : "+f"(c[0]), "+f"(c[1]), "+f"(c[2]), "+f"(c[3])
                 : "r"(a0), "r"(a1), "r"(a2), "r"(a3), "r"(b0), "r"(b1));
}
__device__ __forceinline__ void cp16(uint32_t dst, const void* src) {
    asm volatile("cp.async.cg.shared.global [%0], [%1], 16;"
                 :: "r"(dst), "l"(__cvta_generic_to_global(src)) : "memory");
}
__device__ __forceinline__ uint32_t smem_u32(const void* p) {
    uint32_t a;
    asm("{ .reg .u64 t; cvta.to.shared.u64 t, %1; cvt.u32.u64 %0, t; }" : "=r"(a) : "l"(p));
    return a;
}

#define HST 32768                     // bytes per stage (A 16K + B 16K)
#define SH_A(s) ((s)*HST)
#define SH_B(s) ((s)*HST + 16384)
#define SMEM_H  (3*HST)               // 98304 bytes

// ============================================================================
// GEMM-H (fp16, cp.async 3-stage pipeline): weight GEMMs
//   C[M=4096, N] = A[M, K] @ W[N, K]^T  then *s[col] (+bias) (+res)
// LAYOUT: 0 = fp32 o0[r*ldc+c]
//         3 = merged QKV: c<2048 -> q head layout (o0), c<4096 -> k (o1),
//             else V^T (o2); all fp16
// ============================================================================
template<int LAYOUT, bool HAS_BIAS, bool HAS_RES>
__global__ void __launch_bounds__(256) gemm_h(
    const __half* __restrict__ A, const __half* __restrict__ W, int K,
    const float* __restrict__ s, const float* __restrict__ bias,
    const float* __restrict__ res, void* __restrict__ o0,
    void* __restrict__ o1, void* __restrict__ o2, int ldc)
{
    extern __shared__ char smem[];
    const uint32_t sb = smem_u32(smem);
    const int tid = threadIdx.x, lane = tid & 31, w = tid >> 5;
    const int wm = w & 1, wn = w >> 1;           // warp grid 2(M) x 4(N)
    const int m0 = blockIdx.y * 128, n0 = blockIdx.x * 128;
    const int KB = K >> 6;

    const __half* Ag = A + (long)m0 * K;
    const __half* Bg = W + (long)n0 * K;

    const int lr = tid >> 3, lj = tid & 7;

    auto load_stage = [&](int st, int kb) {
        const __half* a = Ag + kb * 64;
        const __half* b = Bg + kb * 64;
        #pragma unroll
        for (int i = 0; i < 4; i++) {
            int r = lr + i * 32;
            uint32_t dsw = r * 128 + ((lj ^ (r & 7)) * 16);
            cp16(sb + SH_A(st) + dsw, a + (long)r * K + lj * 8);
        }
        #pragma unroll
        for (int i = 0; i < 4; i++) {
            int r = lr + i * 32;
            uint32_t dsw = r * 128 + ((lj ^ (r & 7)) * 16);
            cp16(sb + SH_B(st) + dsw, b + (long)r * K + lj * 8);
        }
        asm volatile("cp.async.commit_group;" ::: "memory");
    };

    float acc[4][4][4];
    #pragma unroll
    for (int i = 0; i < 4; i++)
        #pragma unroll
        for (int j = 0; j < 4; j++)
            #pragma unroll
            for (int e = 0; e < 4; e++) acc[i][j][e] = 0.f;

    load_stage(0, 0);
    if (KB > 1) load_stage(1, 1);

    for (int kb = 0; kb < KB; kb++) {
        const int st = kb % 3;
        if (kb + 1 < KB) { asm volatile("cp.async.wait_group 1;" ::: "memory"); }
        else             { asm volatile("cp.async.wait_group 0;" ::: "memory"); }
        __syncthreads();
        if (kb + 2 < KB) load_stage((kb + 2) % 3, kb + 2);

        const uint32_t aB = sb + SH_A(st), bB = sb + SH_B(st);
        #pragma unroll
        for (int ks = 0; ks < 4; ks++) {
            const int kk0 = ks * 16;
            uint32_t af[4][4], bf[4][2];
            #pragma unroll
            for (int i = 0; i < 4; i++) {
                int ra = wm * 64 + i * 16 + (lane & 15);
                int kk = kk0 + (lane >> 4) * 8;
                uint32_t ad = aB + ra * 128 + (((kk >> 3) ^ (ra & 7)) * 16);
                ldsm_x4(af[i][0], af[i][1], af[i][2], af[i][3], ad);
            }
            #pragma unroll
            for (int j = 0; j < 4; j++) {
                int rb = wn * 32 + j * 8 + (lane & 7);
                int kk = kk0 + ((lane >> 3) & 1) * 8;
                uint32_t bd = bB + rb * 128 + (((kk >> 3) ^ (rb & 7)) * 16);
                ldsm_x2(bf[j][0], bf[j][1], bd);
            }
            #pragma unroll
            for (int i = 0; i < 4; i++)
                #pragma unroll
                for (int j = 0; j < 4; j++)
                    mma16816h(acc[i][j], af[i][0], af[i][1], af[i][2], af[i][3], bf[j][0], bf[j][1]);
        }
    }

    // --- epilogue ---
    const int gr = lane >> 2, gc = (lane & 3) * 2;
    #pragma unroll
    for (int i = 0; i < 4; i++) {
        #pragma unroll
        for (int j = 0; j < 4; j++) {
            int rbase = m0 + wm * 64 + i * 16 + gr;
            int cbase = n0 + wn * 32 + j * 8 + gc;
            #pragma unroll
            for (int e = 0; e < 4; e++) {
                int r = rbase + (e >> 1) * 8;
                int c = cbase + (e & 1);
                float v = acc[i][j][e] * s[c];
                if (HAS_BIAS) v += bias[c];
                if (HAS_RES)  v += res[(long)r * D_MODEL + c];
                if (LAYOUT == 0) {
                    ((float*)o0)[(long)r * ldc + c] = v;
                } else {
                    int b = r >> 10, t = r & 1023;
                    int mat = c >> 11, cc = c & 2047;
                    int h = cc >> 7, d = cc & 127;
                    long base = (long)(b * N_HEADS + h) * (TT * DH);
                    long idx = base + ((mat == 2) ? ((long)d * TT + t) : ((long)t * DH + d));
                    __half* o = (mat == 0) ? (__half*)o0 : ((mat == 1) ? (__half*)o1 : (__half*)o2);
                    o[idx] = __float2half_rn(v);
                }
            }
        }
    }
}

// ============================================================================
// GEMM-A (fp16 batched, cp.async 3-stage pipeline): attention GEMMs
//   C[z][M,N] = A[z][M,K] @ B[z][N,K]^T
// EPI 0: scores -> fp32 * 1/sqrt(128) at sc[z][r][c]
// EPI 1: P@V    -> fp32 at[(b*TT+r)*D_MODEL + h*DH + c],  b=z>>4, h=z&15
// ============================================================================
template<int EPI>
__global__ void __launch_bounds__(256) gemm_a(
    const __half* __restrict__ Ab, const __half* __restrict__ Bb,
    float* __restrict__ outb, int K, long sAz, long sBz)
{
    extern __shared__ char smem[];
    const uint32_t sb = smem_u32(smem);
    const int tid = threadIdx.x, lane = tid & 31, w = tid >> 5;
    const int wm = w & 1, wn = w >> 1;
    const int z = blockIdx.z;
    const int m0 = blockIdx.y * 128, n0 = blockIdx.x * 128;
    const int KB = K >> 6;

    const __half* Ag = Ab + (long)z * sAz + (long)m0 * K;
    const __half* Bg = Bb + (long)z * sBz + (long)n0 * K;

    const int lr = tid >> 3, lj = tid & 7;

    auto load_stage = [&](int st, int kb) {
        const __half* a = Ag + kb * 64;
        const __half* b = Bg + kb * 64;
        #pragma unroll
        for (int i = 0; i < 4; i++) {
            int r = lr + i * 32;
            uint32_t dsw = r * 128 + ((lj ^ (r & 7)) * 16);
            cp16(sb + SH_A(st) + dsw, a + (long)r * K + lj * 8);
        }
        #pragma unroll
        for (int i = 0; i < 4; i++) {
            int r = lr + i * 32;
            uint32_t dsw = r * 128 + ((lj ^ (r & 7)) * 16);
            cp16(sb + SH_B(st) + dsw, b + (long)r * K + lj * 8);
        }
        asm volatile("cp.async.commit_group;" ::: "memory");
    };

    float acc[4][4][4];
    #pragma unroll
    for (int i = 0; i < 4; i++)
        #pragma unroll
        for (int j = 0; j < 4; j++)
            #pragma unroll
            for (int e = 0; e < 4; e++) acc[i][j][e] = 0.f;

    load_stage(0, 0);
    if (KB > 1) load_stage(1, 1);

    for (int kb = 0; kb < KB; kb++) {
        const int st = kb % 3;
        if (kb + 1 < KB) { asm volatile("cp.async.wait_group 1;" ::: "memory"); }
        else             { asm volatile("cp.async.wait_group 0;" ::: "memory"); }
        __syncthreads();
        if (kb + 2 < KB) load_stage((kb + 2) % 3, kb + 2);

        const uint32_t aB = sb + SH_A(st), bB = sb + SH_B(st);
        #pragma unroll
        for (int ks = 0; ks < 4; ks++) {
            const int kk0 = ks * 16;
            uint32_t af[4][4], bf[4][2];
            #pragma unroll
            for (int i = 0; i < 4; i++) {
                int ra = wm * 64 + i * 16 + (lane & 15);
                int kk = kk0 + (lane >> 4) * 8;
                uint32_t ad = aB + ra * 128 + (((kk >> 3) ^ (ra & 7)) * 16);
                ldsm_x4(af[i][0], af[i][1], af[i][2], af[i][3], ad);
            }
            #pragma unroll
            for (int j = 0; j < 4; j++) {
                int rb = wn * 32 + j * 8 + (lane & 7);
                int kk = kk0 + ((lane >> 3) & 1) * 8;
                uint32_t bd = bB + rb * 128 + (((kk >> 3) ^ (rb & 7)) * 16);
                ldsm_x2(bf[j][0], bf[j][1], bd);
            }
            #pragma unroll
            for (int i = 0; i < 4; i++)
                #pragma unroll
                for (int j = 0; j < 4; j++)
                    mma16816h(acc[i][j], af[i][0], af[i][1], af[i][2], af[i][3], bf[j][0], bf[j][1]);
        }
    }

    const int gr = lane >> 2, gc = (lane & 3) * 2;
    #pragma unroll
    for (int i = 0; i < 4; i++) {
        #pragma unroll
        for (int j = 0; j < 4; j++) {
            int rbase = m0 + wm * 64 + i * 16 + gr;
            int cbase = n0 + wn * 32 + j * 8 + gc;
            #pragma unroll
            for (int e = 0; e < 4; e++) {
                int r = rbase + (e >> 1) * 8;
                int c = cbase + (e & 1);
                float v = acc[i][j][e];
                if (EPI == 0) {
                    outb[(long)z * TT * TT + (long)r * TT + c] = v * 0.08838834764831845f;
                } else {
                    int b = z >> 4, h = z & 15;
                    outb[((long)(b * TT + r)) * D_MODEL + h * DH + c] = v;
                }
            }
        }
    }
}

// ---------------- reductions ----------------
__device__ __forceinline__ float warp_sum(float v) {
    #pragma unroll
    for (int o = 16; o; o >>= 1) v += __shfl_xor_sync(0xffffffffu, v, o);
    return v;
}
__device__ __forceinline__ float warp_max(float v) {
    #pragma unroll
    for (int o = 16; o; o >>= 1) v = fmaxf(v, __shfl_xor_sync(0xffffffffu, v, o));
    return v;
}
template<int NW>
__device__ __forceinline__ float block_sum(float v, float* buf) {
    int tid = threadIdx.x;
    v = warp_sum(v);
    __syncthreads();
    if ((tid & 31) == 0) buf[tid >> 5] = v;
    __syncthreads();
    if (tid == 0) { float t = 0; for (int i = 0; i < NW; i++) t += buf[i]; buf[0] = t; }
    __syncthreads();
    return buf[0];
}
template<int NW>
__device__ __forceinline__ float block_max(float v, float* buf) {
    int tid = threadIdx.x;
    v = warp_max(v);
    __syncthreads();
    if ((tid & 31) == 0) buf[tid >> 5] = v;
    __syncthreads();
    if (tid == 0) { float t = buf[0]; for (int i = 1; i < NW; i++) t = fmaxf(t, buf[i]); buf[0] = t; }
    __syncthreads();
    return buf[0];
}

// ------- LN (optional) + Hadamard-2048 -> fp16, one block/token -------
template<bool DO_LN>
__global__ void __launch_bounds__(256) ln_had2048(
    const float* __restrict__ in, const float* __restrict__ g,
    const float* __restrict__ bta, __half* __restrict__ outs)
{
    __shared__ float s[2048];
    __shared__ float red[8];
    const int tid = threadIdx.x;
    const float* x = in + (long)blockIdx.x * 2048;
    float loc[8];
    #pragma unroll
    for (int j = 0; j < 8; j++) loc[j] = x[tid + 256 * j];

    if (DO_LN) {
        float sm = 0.f, sq = 0.f;
        #pragma unroll
        for (int j = 0; j < 8; j++) { sm += loc[j]; sq += loc[j] * loc[j]; }
        float S  = block_sum<8>(sm, red);
        float SQ = block_sum<8>(sq, red);
        float mu = S * (1.0f / 2048.0f);
        float var = SQ * (1.0f / 2048.0f) - mu * mu;
        float inv = rsqrtf(var + 1e-5f);
        #pragma unroll
        for (int j = 0; j < 8; j++) {
            int c = tid + 256 * j;
            loc[j] = (loc[j] - mu) * inv * g[c] + bta[c];
        }
    }
    #pragma unroll
    for (int j = 0; j < 8; j++) s[tid + 256 * j] = loc[j];

    int sh = 0;
    for (int h = 1; h < 2048; h <<= 1, sh++) {
        __syncthreads();
        #pragma unroll
        for (int j = 0; j < 4; j++) {
            int pi = tid + 256 * j;
            int idx = ((pi >> sh) << (sh + 1)) + (pi & (h - 1));
            float a = s[idx], c = s[idx + h];
            s[idx] = a + c;
            s[idx + h] = a - c;
        }
    }
    __syncthreads();
    __half* o = outs + (long)blockIdx.x * 2048;
    #pragma unroll
    for (int j = 0; j < 8; j++) {
        int c = tid + 256 * j;
        o[c] = __float2half_rn(s[c] * 0.022097086912079608f);
    }
}

// ------- GELU(exact) + Hadamard-8192 -> fp16, one block/token -------
__global__ void __launch_bounds__(512) gelu_had8192(const float* __restrict__ in, __half* __restrict__ outs)
{
    __shared__ float s[8192];
    const int tid = threadIdx.x;
    const float* x = in + (long)blockIdx.x * 8192;
    #pragma unroll
    for (int j = 0; j < 16; j++) {
        float v = x[tid + 512 * j];
        v = 0.5f * v * (1.0f + erff(v * 0.7071067811865476f));
        s[tid + 512 * j] = v;
    }
    int sh = 0;
    for (int h = 1; h < 8192; h <<= 1, sh++) {
        __syncthreads();
        #pragma unroll
        for (int j = 0; j < 8; j++) {
            int pi = tid + 512 * j;
            int idx = ((pi >> sh) << (sh + 1)) + (pi & (h - 1));
            float a = s[idx], c = s[idx + h];
            s[idx] = a + c;
            s[idx + h] = a - c;
        }
    }
    __syncthreads();
    __half* o = outs + (long)blockIdx.x * 8192;
    #pragma unroll
    for (int j = 0; j < 16; j++) {
        int c = tid + 512 * j;
        o[c] = __float2half_rn(s[c] * 0.011048543456039806f);
    }
}

// ------ softmax over rows of 1024: fp32 scores in -> fp16 probs out ------
__global__ void __launch_bounds__(256) softmax1024(const float* __restrict__ sc, __half* __restrict__ pout)
{
    __shared__ float red[8];
    const int tid = threadIdx.x;
    const float* row = sc + (long)blockIdx.x * 1024;
    __half* orow = pout + (long)blockIdx.x * 1024;
    float v[4];
    float mx = -3.4e38f;
    #pragma unroll
    for (int j = 0; j < 4; j++) { v[j] = row[tid + 256 * j]; mx = fmaxf(mx, v[j]); }
    float m = block_max<8>(mx, red);
    float sm = 0.f;
    #pragma unroll
    for (int j = 0; j < 4; j++) { v[j] = __expf(v[j] - m); sm += v[j]; }
    float S = block_sum<8>(sm, red);
    float inv = 1.0f / S;
    #pragma unroll
    for (int j = 0; j < 4; j++) orow[tid + 256 * j] = __float2half_rn(v[j] * inv);
}

// ============================================================================
extern "C" void kernel_launch(void* const* d_in, const int* in_sizes, int n_in,
                              void* d_out, int out_size)
{
    const float*  x    = (const float*) d_in[0];
    const float*  ln1g = (const float*) d_in[1];
    const float*  ln1b = (const float*) d_in[2];
    const float*  ln2g = (const float*) d_in[3];
    const float*  ln2b = (const float*) d_in[4];
    const void*   Qq   = d_in[5];
    const float*  sq   = (const float*) d_in[6];
    const void*   Qk   = d_in[7];
    const float*  sk   = (const float*) d_in[8];
    const void*   Qv   = d_in[9];
    const float*  sv   = (const float*) d_in[10];
    const void*   Qo   = d_in[11];
    const float*  so   = (const float*) d_in[12];
    const void*   Qf1  = d_in[13];
    const float*  sf1  = (const float*) d_in[14];
    const float*  bf1  = (const float*) d_in[15];
    const void*   Qf2  = d_in[16];
    const float*  sf2  = (const float*) d_in[17];
    const float*  bf2  = (const float*) d_in[18];
    float* out = (float*)d_out;

    float *sc, *at, *x1, *ff, *s6;
    __half *hd, *hf, *qh, *kh, *vth, *ph, *wb;
    cudaGetSymbolAddress((void**)&sc,  g_sc);
    cudaGetSymbolAddress((void**)&at,  g_at);
    cudaGetSymbolAddress((void**)&x1,  g_x1);
    cudaGetSymbolAddress((void**)&ff,  g_ff);
    cudaGetSymbolAddress((void**)&s6,  g_s6);
    cudaGetSymbolAddress((void**)&hd,  g_hd);
    cudaGetSymbolAddress((void**)&hf,  g_hf);
    cudaGetSymbolAddress((void**)&qh,  g_qh);
    cudaGetSymbolAddress((void**)&kh,  g_kh);
    cudaGetSymbolAddress((void**)&vth, g_vth);
    cudaGetSymbolAddress((void**)&ph,  g_ph);
    cudaGetSymbolAddress((void**)&wb,  g_w);

    __half* wqkv = wb;                 // q,k,v contiguous (3*NWD)
    __half* wo   = wb + 3 * NWD;
    __half* wf1  = wb + 4 * NWD;
    __half* wf2  = wb + 4 * NWD + NWF;

    cudaFuncSetAttribute((const void*)gemm_h<3, false, false>, cudaFuncAttributeMaxDynamicSharedMemorySize, SMEM_H);
    cudaFuncSetAttribute((const void*)gemm_h<0, false, true>,  cudaFuncAttributeMaxDynamicSharedMemorySize, SMEM_H);
    cudaFuncSetAttribute((const void*)gemm_h<0, true, false>,  cudaFuncAttributeMaxDynamicSharedMemorySize, SMEM_H);
    cudaFuncSetAttribute((const void*)gemm_h<0, true, true>,   cudaFuncAttributeMaxDynamicSharedMemorySize, SMEM_H);
    cudaFuncSetAttribute((const void*)gemm_a<0>,               cudaFuncAttributeMaxDynamicSharedMemorySize, SMEM_H);
    cudaFuncSetAttribute((const void*)gemm_a<1>,               cudaFuncAttributeMaxDynamicSharedMemorySize, SMEM_H);

    // launch 0-1: dtype probe
    zero_counters<<<1, 1>>>();
    probe_dtype<<<4096, 256>>>(Qq, 1 << 20);
    // launch 2: q,k,v weights -> contiguous fp16 (vectorized)
    convert_w3<<<(int)((3 * (NWD / 4) + 255) / 256), 256>>>(Qq, Qk, Qv, wqkv, NWD / 4);
    // launch 3: concat scales
    cat_scales<<<24, 256>>>(sq, sk, sv, s6);
    // launch 4: LN1 + Hadamard -> fp16
    ln_had2048<true><<<BT, 256>>>(x, ln1g, ln1b, hd);
    // launch 5 (ncu capture): merged QKV projection, N=6144
    gemm_h<3, false, false><<<dim3(48, 32), 256, SMEM_H>>>(hd, wqkv, D_MODEL, s6, nullptr, nullptr, qh, kh, vth, 0);
    // attention
    gemm_a<0><<<dim3(8, 8, BH), 256, SMEM_H>>>(qh, kh, sc, DH, (long)TT * DH, (long)TT * DH);
    softmax1024<<<BH * TT, 256>>>(sc, ph);
    gemm_a<1><<<dim3(1, 8, BH), 256, SMEM_H>>>(ph, vth, at, TT, (long)TT * TT, (long)DH * TT);
    // Hadamard(attn) -> fp16
    ln_had2048<false><<<BT, 256>>>(at, nullptr, nullptr, hd);
    // O-proj weights + GEMM (x1 = x + O-proj)
    convert_w4<<<(int)((NWD / 4 + 255) / 256), 256>>>(Qo, wo, NWD / 4);
    gemm_h<0, false, true><<<dim3(16, 32), 256, SMEM_H>>>(hd, wo, D_MODEL, so, nullptr, x, x1, nullptr, nullptr, D_MODEL);
    // LN2 + Hadamard -> fp16
    ln_had2048<true><<<BT, 256>>>(x1, ln2g, ln2b, hd);
    // FF1
    convert_w4<<<(int)((NWF / 4 + 255) / 256), 256>>>(Qf1, wf1, NWF / 4);
    gemm_h<0, true, false><<<dim3(64, 32), 256, SMEM_H>>>(hd, wf1, D_MODEL, sf1, bf1, nullptr, ff, nullptr, nullptr, D_FF);
    // GELU + Hadamard-8192 -> fp16
    gelu_had8192<<<BT, 512>>>(ff, hf);
    // FF2 (out = x1 + FF2)
    convert_w4<<<(int)((NWF / 4 + 255) / 256), 256>>>(Qf2, wf2, NWF / 4);
    gemm_h<0, true, true><<<dim3(16, 32), 256, SMEM_H>>>(hf, wf2, D_FF, sf2, bf2, x1, out, nullptr, nullptr, D_MODEL);
}